// round 1
// baseline (speedup 1.0000x reference)
#include <cuda_runtime.h>
#include <math.h>

// ---------------------------------------------------------------------------
// GatedDeltaNet  B=2 S=2048 H=2048 HK=16 HV=32 DK=DV=128 G=2 K=4
// Round 1: fp32 correctness baseline.
//   K1: qkvz = x @ w_qkvz            (SIMT sgemm 128x128x8)
//   K2: ba   = x @ w_ba              (same kernel, guarded N=64)
//   K3: causal depthwise conv + silu (elementwise, gather from qkvz)
//   K4: l2norm(q)*DK^-0.5, l2norm(k)
//   K5: g = -exp(a_log)*softplus(a+dt_bias), beta = sigmoid(b)
//   K6: sequential gated delta scan, 64 blocks (one per b,h),
//       state 128x128 fp32 in registers (256 thr x 64 regs)
//   K7: o * silu(z), RMSNorm * norm_w
//   K8: out = o @ w_o
// ---------------------------------------------------------------------------

#define Sc    2048
#define Hc    2048
#define HKc   16
#define HVc   32
#define Gc    2
#define CDc   8192
#define FQ    12288
#define Mtot  4096
#define EPSc  1e-6f

// scratch (module-scope device arrays; allocation-guard safe)
__device__ float g_qkvz[(size_t)Mtot * FQ];    // 201 MB
__device__ float g_ba[Mtot * 64];
__device__ float g_conv[(size_t)Mtot * CDc];   // 134 MB
__device__ float g_qn[Mtot * 2048];
__device__ float g_kn[Mtot * 2048];
__device__ float g_gg[Mtot * HVc];
__device__ float g_beta[Mtot * HVc];
__device__ float g_opre[(size_t)Mtot * 4096];  // 67 MB
__device__ float g_ofin[(size_t)Mtot * 4096];  // 67 MB

// ---------------------------------------------------------------------------
// SIMT fp32 GEMM: C[M,N] = A[M,K] @ B[K,N], 128x128 block tile, 8x8/thread.
// M % 128 == 0, K % 8 == 0 always hold here. GUARD handles N not % 128 (N%4==0).
// ---------------------------------------------------------------------------
template <bool GUARD>
__global__ void __launch_bounds__(256) sgemm_kernel(
    const float* __restrict__ A, const float* __restrict__ Bm,
    float* __restrict__ C, int M, int N, int Kd)
{
    __shared__ float As[8][128];   // transposed A tile: As[k][m]
    __shared__ float Bs[8][128];

    int t  = threadIdx.x;
    int bx = blockIdx.x, by = blockIdx.y;
    int tx = t & 15, ty = t >> 4;

    float acc[8][8];
#pragma unroll
    for (int i = 0; i < 8; i++)
#pragma unroll
        for (int j = 0; j < 8; j++) acc[i][j] = 0.f;

    int arow  = t >> 1;        // 0..127
    int acol4 = (t & 1) * 4;   // 0 or 4
    int brow  = t >> 5;        // 0..7
    int bcol4 = (t & 31) * 4;  // 0..124
    const float* Aptr = A + (size_t)(by * 128 + arow) * Kd;
    int bcolg = bx * 128 + bcol4;

    for (int k0 = 0; k0 < Kd; k0 += 8) {
        float4 a4 = *reinterpret_cast<const float4*>(Aptr + k0 + acol4);
        As[acol4 + 0][arow] = a4.x;
        As[acol4 + 1][arow] = a4.y;
        As[acol4 + 2][arow] = a4.z;
        As[acol4 + 3][arow] = a4.w;
        float4 b4 = make_float4(0.f, 0.f, 0.f, 0.f);
        if (!GUARD || bcolg < N)
            b4 = *reinterpret_cast<const float4*>(Bm + (size_t)(k0 + brow) * N + bcolg);
        *reinterpret_cast<float4*>(&Bs[brow][bcol4]) = b4;
        __syncthreads();
#pragma unroll
        for (int kk = 0; kk < 8; kk++) {
            float a[8], b[8];
            *reinterpret_cast<float4*>(a)     = *reinterpret_cast<const float4*>(&As[kk][ty * 8]);
            *reinterpret_cast<float4*>(a + 4) = *reinterpret_cast<const float4*>(&As[kk][ty * 8 + 4]);
            *reinterpret_cast<float4*>(b)     = *reinterpret_cast<const float4*>(&Bs[kk][tx * 8]);
            *reinterpret_cast<float4*>(b + 4) = *reinterpret_cast<const float4*>(&Bs[kk][tx * 8 + 4]);
#pragma unroll
            for (int i = 0; i < 8; i++)
#pragma unroll
                for (int j = 0; j < 8; j++)
                    acc[i][j] = fmaf(a[i], b[j], acc[i][j]);
        }
        __syncthreads();
    }

#pragma unroll
    for (int i = 0; i < 8; i++) {
        int row = by * 128 + ty * 8 + i;
#pragma unroll
        for (int j = 0; j < 8; j += 4) {
            int col = bx * 128 + tx * 8 + j;
            if (!GUARD || col < N) {
                float4 v4 = make_float4(acc[i][j], acc[i][j + 1], acc[i][j + 2], acc[i][j + 3]);
                *reinterpret_cast<float4*>(C + (size_t)row * N + col) = v4;
            }
        }
    }
}

// ---------------------------------------------------------------------------
// causal depthwise conv (K=4) + silu. mixed channel -> qkvz column gather.
//   c in [0,2048):       q : col = hk*768 + d
//   c in [2048,4096):    k : col = hk*768 + 128 + d
//   c in [4096,8192):    v : col = hk*768 + 256 + rem   (rem in [0,256))
// ---------------------------------------------------------------------------
__global__ void conv_silu_kernel(const float* __restrict__ conv_w,
                                 const float* __restrict__ conv_b)
{
    int c = blockIdx.x * 256 + threadIdx.x;  // 0..8191
    int m = blockIdx.y;
    int s = m & (Sc - 1);
    int col;
    if (c < 2048) {
        col = (c >> 7) * 768 + (c & 127);
    } else if (c < 4096) {
        int c2 = c - 2048;
        col = (c2 >> 7) * 768 + 128 + (c2 & 127);
    } else {
        int c3 = c - 4096;
        col = (c3 >> 8) * 768 + 256 + (c3 & 255);
    }
    float acc = conv_b[c];
    const float* w = conv_w + c * 4;
#pragma unroll
    for (int j = 0; j < 4; j++) {
        int sp = s - 3 + j;
        if (sp >= 0)
            acc = fmaf(g_qkvz[(size_t)(m - 3 + j) * FQ + col], w[j], acc);
    }
    g_conv[(size_t)m * CDc + c] = acc / (1.f + expf(-acc));  // silu
}

// ---------------------------------------------------------------------------
// l2norm over DK for q (scaled DK^-0.5) and k. One block per (m, hk).
// ---------------------------------------------------------------------------
__global__ void qknorm_kernel()
{
    int m = blockIdx.x, hk = blockIdx.y, d = threadIdx.x;
    float qv = g_conv[(size_t)m * CDc + hk * 128 + d];
    float kv = g_conv[(size_t)m * CDc + 2048 + hk * 128 + d];
    float sq = qv * qv, sk = kv * kv;
#pragma unroll
    for (int o = 16; o > 0; o >>= 1) {
        sq += __shfl_xor_sync(0xffffffffu, sq, o);
        sk += __shfl_xor_sync(0xffffffffu, sk, o);
    }
    __shared__ float rb[8];
    int w = d >> 5;
    if ((d & 31) == 0) { rb[w] = sq; rb[4 + w] = sk; }
    __syncthreads();
    float sumq = rb[0] + rb[1] + rb[2] + rb[3];
    float sumk = rb[4] + rb[5] + rb[6] + rb[7];
    float rq = rsqrtf(sumq + EPSc) * 0.08838834764831845f;  // DK^-0.5
    float rk = rsqrtf(sumk + EPSc);
    g_qn[m * 2048 + hk * 128 + d] = qv * rq;
    g_kn[m * 2048 + hk * 128 + d] = kv * rk;
}

// ---------------------------------------------------------------------------
// gates: g = -exp(a_log)*softplus(a + dt_bias), beta = sigmoid(b)
// ba layout per hk: [beta0, beta1, a0, a1]
// ---------------------------------------------------------------------------
__global__ void gbeta_kernel(const float* __restrict__ a_log,
                             const float* __restrict__ dt_bias)
{
    int idx = blockIdx.x * 256 + threadIdx.x;  // M*HV = 131072 exact
    int m = idx >> 5, hv = idx & 31;
    int hk = hv >> 1, gi = hv & 1;
    float bval = g_ba[m * 64 + hk * 4 + gi];
    float aval = g_ba[m * 64 + hk * 4 + 2 + gi];
    float x = aval + dt_bias[hv];
    float sp = (x > 20.f) ? x : log1pf(expf(x));
    g_gg[idx]   = -expf(a_log[hv]) * sp;
    g_beta[idx] = 1.f / (1.f + expf(-bval));
}

// ---------------------------------------------------------------------------
// sequential gated delta scan. One block per (b, hv); 256 threads.
// thread t owns rows [half*64, half*64+64) of state column v = t&127.
// Per step:  S *= exp(g);  pred = k.S;  delta = (v - pred)*beta;
//            S += k (x) delta;  o = q.S
// ---------------------------------------------------------------------------
__global__ void __launch_bounds__(256) scan_kernel()
{
    int bh = blockIdx.x;
    int bb = bh >> 5, hv = bh & 31, hk = hv >> 1;
    int t = threadIdx.x;
    int v = t & 127, half = t >> 7, dbase = half * 64;

    float S[64];
#pragma unroll
    for (int i = 0; i < 64; i++) S[i] = 0.f;

    __shared__ float ks[128], qs[128], vs[128];
    __shared__ float predr[2][128], ored[2][128];
    __shared__ float egs, betas;
    int base_qk = hk * 128;

    for (int s = 0; s < Sc; s++) {
        int m = bb * Sc + s;
        if (t < 128) {
            ks[t] = g_kn[m * 2048 + base_qk + t];
            qs[t] = g_qn[m * 2048 + base_qk + t];
            vs[t] = g_conv[(size_t)m * CDc + 4096 + hv * 128 + t];
        }
        if (t == 0) {
            egs   = expf(g_gg[m * 32 + hv]);
            betas = g_beta[m * 32 + hv];
        }
        __syncthreads();

        float eg = egs;
        float pred = 0.f;
#pragma unroll
        for (int d = 0; d < 64; d++) {
            S[d] *= eg;
            pred = fmaf(ks[dbase + d], S[d], pred);
        }
        predr[half][v] = pred;
        __syncthreads();

        float delta = (vs[v] - predr[0][v] - predr[1][v]) * betas;
        float o = 0.f;
#pragma unroll
        for (int d = 0; d < 64; d++) {
            S[d] = fmaf(ks[dbase + d], delta, S[d]);
            o = fmaf(qs[dbase + d], S[d], o);
        }
        ored[half][v] = o;
        __syncthreads();

        if (t < 128)
            g_opre[(size_t)m * 4096 + hv * 128 + t] = ored[0][t] + ored[1][t];
    }
}

// ---------------------------------------------------------------------------
// o * silu(z), then RMSNorm over DV with norm_w. One block per (m, hv).
// z at qkvz col hk*768 + 512 + gi*128 + d.
// ---------------------------------------------------------------------------
__global__ void gate_norm_kernel(const float* __restrict__ norm_w)
{
    int m = blockIdx.x, hv = blockIdx.y, d = threadIdx.x;
    int hk = hv >> 1, gi = hv & 1;
    float z = g_qkvz[(size_t)m * FQ + hk * 768 + 512 + gi * 128 + d];
    float o = g_opre[(size_t)m * 4096 + hv * 128 + d] * (z / (1.f + expf(-z)));
    float ss = o * o;
#pragma unroll
    for (int off = 16; off > 0; off >>= 1) ss += __shfl_xor_sync(0xffffffffu, ss, off);
    __shared__ float rb[4];
    if ((d & 31) == 0) rb[d >> 5] = ss;
    __syncthreads();
    float sum = rb[0] + rb[1] + rb[2] + rb[3];
    float rs = rsqrtf(sum * (1.f / 128.f) + EPSc);
    g_ofin[(size_t)m * 4096 + hv * 128 + d] = o * rs * norm_w[d];
}

// ---------------------------------------------------------------------------
extern "C" void kernel_launch(void* const* d_in, const int* in_sizes, int n_in,
                              void* d_out, int out_size)
{
    const float* x       = (const float*)d_in[0];
    const float* w_qkvz  = (const float*)d_in[1];
    const float* w_ba    = (const float*)d_in[2];
    const float* a_log   = (const float*)d_in[3];
    const float* dt_bias = (const float*)d_in[4];
    const float* conv_w  = (const float*)d_in[5];
    const float* conv_b  = (const float*)d_in[6];
    const float* norm_w  = (const float*)d_in[7];
    const float* w_o     = (const float*)d_in[8];
    float* out = (float*)d_out;

    float *p_qkvz, *p_ba, *p_ofin;
    cudaGetSymbolAddress((void**)&p_qkvz, g_qkvz);
    cudaGetSymbolAddress((void**)&p_ba,   g_ba);
    cudaGetSymbolAddress((void**)&p_ofin, g_ofin);

    // K1: qkvz = x @ w_qkvz   [4096,2048]@[2048,12288]
    sgemm_kernel<false><<<dim3(FQ / 128, Mtot / 128), 256>>>(x, w_qkvz, p_qkvz, Mtot, FQ, Hc);
    // K2: ba = x @ w_ba       [4096,2048]@[2048,64]
    sgemm_kernel<true><<<dim3(1, Mtot / 128), 256>>>(x, w_ba, p_ba, Mtot, 64, Hc);
    // K3: conv + silu
    conv_silu_kernel<<<dim3(CDc / 256, Mtot), 256>>>(conv_w, conv_b);
    // K4: q/k l2norm
    qknorm_kernel<<<dim3(Mtot, HKc), 128>>>();
    // K5: gates
    gbeta_kernel<<<(Mtot * HVc) / 256, 256>>>(a_log, dt_bias);
    // K6: recurrent scan
    scan_kernel<<<2 * HVc, 256>>>();
    // K7: gate + rmsnorm
    gate_norm_kernel<<<dim3(Mtot, HVc), 128>>>(norm_w);
    // K8: out = ofin @ w_o    [4096,4096]@[4096,2048]
    sgemm_kernel<false><<<dim3(Hc / 128, Mtot / 128), 256>>>(p_ofin, w_o, out, Mtot, Hc, 4096);
}

// round 3
// speedup vs baseline: 1.4597x; 1.4597x over previous
#include <cuda_runtime.h>
#include <cuda_bf16.h>
#include <math.h>
#include <stdint.h>

// ---------------------------------------------------------------------------
// GatedDeltaNet  B=2 S=2048 H=2048 HK=16 HV=32 DK=DV=128 G=2 K=4
// Round 3: tensor-core GEMMs via mma.sync (base sm_100 legal; tcgen05 is
// arch-feature-gated and the harness compiles compute_100 without 'a').
//   prep: split x -> bf16 hi/lo; transpose+split w_qkvz, w_o
//   K1: qkvz = x @ w_qkvz   (mma.sync bf16 3-plane, fp32 accum)
//   K2: ba   = x @ w_ba     (SIMT, tiny)
//   K3 conv+silu  K4 l2norm  K5 gates  K6 scan  K7 gate+rmsnorm
//   K8: out = o @ w_o       (mma.sync)
// ---------------------------------------------------------------------------

#define Sc    2048
#define Hc    2048
#define HKc   16
#define HVc   32
#define CDc   8192
#define FQ    12288
#define Mtot  4096
#define EPSc  1e-6f

// ------------------------------ scratch ------------------------------------
__device__ float g_qkvz[(size_t)Mtot * FQ];
__device__ float g_ba[Mtot * 64];
__device__ float g_conv[(size_t)Mtot * CDc];
__device__ float g_qn[Mtot * 2048];
__device__ float g_kn[Mtot * 2048];
__device__ float g_gg[Mtot * HVc];
__device__ float g_beta[Mtot * HVc];
__device__ float g_opre[(size_t)Mtot * 4096];
__device__ float g_ofin[(size_t)Mtot * 4096];

__device__ __nv_bfloat16 g_xhi[(size_t)Mtot * Hc];
__device__ __nv_bfloat16 g_xlo[(size_t)Mtot * Hc];
__device__ __nv_bfloat16 g_bqhi[(size_t)FQ * Hc];     // w_qkvz^T [12288,2048]
__device__ __nv_bfloat16 g_bqlo[(size_t)FQ * Hc];
__device__ __nv_bfloat16 g_bohi[(size_t)Hc * 4096];   // w_o^T   [2048,4096]
__device__ __nv_bfloat16 g_bolo[(size_t)Hc * 4096];
__device__ __nv_bfloat16 g_ohi[(size_t)Mtot * 4096];
__device__ __nv_bfloat16 g_olo[(size_t)Mtot * 4096];

// ------------------------------ helpers ------------------------------------
__device__ __forceinline__ uint32_t smem_u32(const void* p) {
    uint32_t a;
    asm("{ .reg .u64 t; cvta.to.shared.u64 t, %1; cvt.u32.u64 %0, t; }"
        : "=r"(a) : "l"(p));
    return a;
}
__device__ __forceinline__ void cp_async16(uint32_t saddr, const void* gaddr) {
    asm volatile("cp.async.cg.shared.global [%0], [%1], 16;"
                 :: "r"(saddr), "l"(gaddr) : "memory");
}
__device__ __forceinline__ void cp_commit() {
    asm volatile("cp.async.commit_group;" ::: "memory");
}
template <int N>
__device__ __forceinline__ void cp_wait() {
    asm volatile("cp.async.wait_group %0;" :: "n"(N) : "memory");
}
__device__ __forceinline__ void mma16816(float* c, const uint32_t* a, const uint32_t* b) {
    asm volatile(
        "mma.sync.aligned.m16n8k16.row.col.f32.bf16.bf16.f32 "
        "{%0,%1,%2,%3}, {%4,%5,%6,%7}, {%8,%9}, {%0,%1,%2,%3};"
        : "+f"(c[0]), "+f"(c[1]), "+f"(c[2]), "+f"(c[3])
        : "r"(a[0]), "r"(a[1]), "r"(a[2]), "r"(a[3]), "r"(b[0]), "r"(b[1]));
}

// ---------------------------------------------------------------------------
// mma.sync split-bf16 GEMM: C[M,N] = Ah*Bh^T + Ah*Bl^T + Al*Bh^T
// A planes [M,Kd] row-major bf16; B planes [N,Kd] row-major bf16 (W^T).
// block tile 128x128, 8 warps (4M x 2N), warp tile 32x64, K chunk 32,
// cp.async double-buffered. Row stride in smem = 40 halves (80B, no conflicts).
// ---------------------------------------------------------------------------
#define RS 40   // smem row stride in halves

__global__ void __launch_bounds__(256) mma_gemm_kernel(
    const __nv_bfloat16* __restrict__ Ah, const __nv_bfloat16* __restrict__ Al,
    const __nv_bfloat16* __restrict__ Bh, const __nv_bfloat16* __restrict__ Bl,
    float* __restrict__ C, int Kd, int N)
{
    __shared__ __align__(16) __nv_bfloat16 sA[2][128 * RS];
    __shared__ __align__(16) __nv_bfloat16 sB[2][128 * RS];

    const int t = threadIdx.x, lane = t & 31, w = t >> 5;
    const int wm = (w & 3) * 32, wn = (w >> 2) * 64;
    const int grp = lane >> 2, q = lane & 3;
    const int bx = blockIdx.x, by = blockIdx.y;

    const int kiters = Kd >> 5;
    const int NIT = 3 * kiters;

    float acc[2][8][4];
#pragma unroll
    for (int mi = 0; mi < 2; mi++)
#pragma unroll
        for (int ni = 0; ni < 8; ni++)
#pragma unroll
            for (int j = 0; j < 4; j++) acc[mi][ni][j] = 0.f;

    // per-thread load slots: 2 chunks each for A and B (512 uint4 per tile)
    const int c0 = t, c1 = t + 256;
    const int r0 = c0 >> 2, s0 = c0 & 3;
    const int r1 = c1 >> 2, s1 = c1 & 3;

    uint32_t sA0 = smem_u32(&sA[0][0]), sA1 = smem_u32(&sA[1][0]);
    uint32_t sB0 = smem_u32(&sB[0][0]), sB1 = smem_u32(&sB[1][0]);

    auto issue = [&](int buf, int it) {
        int p = it / kiters, kc = it % kiters;
        const __nv_bfloat16* Ap = (p == 2) ? Al : Ah;
        const __nv_bfloat16* Bp = (p == 1) ? Bl : Bh;
        size_t k0 = (size_t)kc << 5;
        uint32_t sa = buf ? sA1 : sA0;
        uint32_t sb = buf ? sB1 : sB0;
        cp_async16(sa + (r0 * RS + s0 * 8) * 2,
                   Ap + (size_t)(by * 128 + r0) * Kd + k0 + s0 * 8);
        cp_async16(sa + (r1 * RS + s1 * 8) * 2,
                   Ap + (size_t)(by * 128 + r1) * Kd + k0 + s1 * 8);
        cp_async16(sb + (r0 * RS + s0 * 8) * 2,
                   Bp + (size_t)(bx * 128 + r0) * Kd + k0 + s0 * 8);
        cp_async16(sb + (r1 * RS + s1 * 8) * 2,
                   Bp + (size_t)(bx * 128 + r1) * Kd + k0 + s1 * 8);
        cp_commit();
    };

    issue(0, 0);

    for (int it = 0; it < NIT; it++) {
        int buf = it & 1;
        if (it + 1 < NIT) { issue(buf ^ 1, it + 1); cp_wait<1>(); }
        else              { cp_wait<0>(); }
        __syncthreads();

        const __nv_bfloat16* sa = sA[buf];
        const __nv_bfloat16* sb = sB[buf];
#pragma unroll
        for (int ks = 0; ks < 2; ks++) {
            const int k16 = ks * 16;
            uint32_t afr[2][4];
#pragma unroll
            for (int mi = 0; mi < 2; mi++) {
                int ra = wm + mi * 16 + grp;
                afr[mi][0] = *reinterpret_cast<const uint32_t*>(&sa[ra * RS + k16 + q * 2]);
                afr[mi][1] = *reinterpret_cast<const uint32_t*>(&sa[(ra + 8) * RS + k16 + q * 2]);
                afr[mi][2] = *reinterpret_cast<const uint32_t*>(&sa[ra * RS + k16 + 8 + q * 2]);
                afr[mi][3] = *reinterpret_cast<const uint32_t*>(&sa[(ra + 8) * RS + k16 + 8 + q * 2]);
            }
            uint32_t bfr[8][2];
#pragma unroll
            for (int ni = 0; ni < 8; ni++) {
                int cb = wn + ni * 8 + grp;
                bfr[ni][0] = *reinterpret_cast<const uint32_t*>(&sb[cb * RS + k16 + q * 2]);
                bfr[ni][1] = *reinterpret_cast<const uint32_t*>(&sb[cb * RS + k16 + 8 + q * 2]);
            }
#pragma unroll
            for (int mi = 0; mi < 2; mi++)
#pragma unroll
                for (int ni = 0; ni < 8; ni++)
                    mma16816(acc[mi][ni], afr[mi], bfr[ni]);
        }
        __syncthreads();
    }

    // epilogue
#pragma unroll
    for (int mi = 0; mi < 2; mi++) {
        int row = by * 128 + wm + mi * 16 + grp;
#pragma unroll
        for (int ni = 0; ni < 8; ni++) {
            int col = bx * 128 + wn + ni * 8 + q * 2;
            float2 v0 = make_float2(acc[mi][ni][0], acc[mi][ni][1]);
            float2 v1 = make_float2(acc[mi][ni][2], acc[mi][ni][3]);
            *reinterpret_cast<float2*>(C + (size_t)row * N + col) = v0;
            *reinterpret_cast<float2*>(C + (size_t)(row + 8) * N + col) = v1;
        }
    }
}

// ---------------------------------------------------------------------------
// split fp32 -> bf16 hi/lo
// ---------------------------------------------------------------------------
__global__ void split_kernel(const float* __restrict__ src,
                             __nv_bfloat16* __restrict__ hi,
                             __nv_bfloat16* __restrict__ lo)
{
    size_t i = (size_t)blockIdx.x * 256 + threadIdx.x;
    float v = src[i];
    __nv_bfloat16 h = __float2bfloat16(v);
    hi[i] = h;
    lo[i] = __float2bfloat16(v - __bfloat162float(h));
}

// transpose + split: W[K,N] fp32 -> Th/Tl[N,K] bf16
__global__ void transpose_split_kernel(const float* __restrict__ W,
                                       __nv_bfloat16* __restrict__ Th,
                                       __nv_bfloat16* __restrict__ Tl,
                                       int K, int N)
{
    __shared__ float tile[32][33];
    int n0 = blockIdx.x * 32, k0 = blockIdx.y * 32;
    int tx = threadIdx.x, ty = threadIdx.y;
#pragma unroll
    for (int j = 0; j < 4; j++)
        tile[ty + j * 8][tx] = W[(size_t)(k0 + ty + j * 8) * N + n0 + tx];
    __syncthreads();
#pragma unroll
    for (int j = 0; j < 4; j++) {
        float v = tile[tx][ty + j * 8];
        __nv_bfloat16 h = __float2bfloat16(v);
        size_t o = (size_t)(n0 + ty + j * 8) * K + k0 + tx;
        Th[o] = h;
        Tl[o] = __float2bfloat16(v - __bfloat162float(h));
    }
}

// ---------------------------------------------------------------------------
// SIMT fp32 GEMM (tiny ba GEMM only)
// ---------------------------------------------------------------------------
template <bool GUARD>
__global__ void __launch_bounds__(256) sgemm_kernel(
    const float* __restrict__ A, const float* __restrict__ Bm,
    float* __restrict__ C, int M, int N, int Kd)
{
    __shared__ float As[8][128];
    __shared__ float Bs[8][128];
    int t = threadIdx.x;
    int bx = blockIdx.x, by = blockIdx.y;
    int tx = t & 15, ty = t >> 4;
    float acc[8][8];
#pragma unroll
    for (int i = 0; i < 8; i++)
#pragma unroll
        for (int j = 0; j < 8; j++) acc[i][j] = 0.f;
    int arow = t >> 1, acol4 = (t & 1) * 4;
    int brow = t >> 5, bcol4 = (t & 31) * 4;
    const float* Aptr = A + (size_t)(by * 128 + arow) * Kd;
    int bcolg = bx * 128 + bcol4;
    for (int k0 = 0; k0 < Kd; k0 += 8) {
        float4 a4 = *reinterpret_cast<const float4*>(Aptr + k0 + acol4);
        As[acol4 + 0][arow] = a4.x; As[acol4 + 1][arow] = a4.y;
        As[acol4 + 2][arow] = a4.z; As[acol4 + 3][arow] = a4.w;
        float4 b4 = make_float4(0.f, 0.f, 0.f, 0.f);
        if (!GUARD || bcolg < N)
            b4 = *reinterpret_cast<const float4*>(Bm + (size_t)(k0 + brow) * N + bcolg);
        *reinterpret_cast<float4*>(&Bs[brow][bcol4]) = b4;
        __syncthreads();
#pragma unroll
        for (int kk = 0; kk < 8; kk++) {
            float a[8], b[8];
            *reinterpret_cast<float4*>(a)     = *reinterpret_cast<const float4*>(&As[kk][ty * 8]);
            *reinterpret_cast<float4*>(a + 4) = *reinterpret_cast<const float4*>(&As[kk][ty * 8 + 4]);
            *reinterpret_cast<float4*>(b)     = *reinterpret_cast<const float4*>(&Bs[kk][tx * 8]);
            *reinterpret_cast<float4*>(b + 4) = *reinterpret_cast<const float4*>(&Bs[kk][tx * 8 + 4]);
#pragma unroll
            for (int i = 0; i < 8; i++)
#pragma unroll
                for (int j = 0; j < 8; j++)
                    acc[i][j] = fmaf(a[i], b[j], acc[i][j]);
        }
        __syncthreads();
    }
#pragma unroll
    for (int i = 0; i < 8; i++) {
        int row = by * 128 + ty * 8 + i;
#pragma unroll
        for (int j = 0; j < 8; j += 4) {
            int col = bx * 128 + tx * 8 + j;
            if (!GUARD || col < N) {
                float4 v4 = make_float4(acc[i][j], acc[i][j + 1], acc[i][j + 2], acc[i][j + 3]);
                *reinterpret_cast<float4*>(C + (size_t)row * N + col) = v4;
            }
        }
    }
}

// ---------------------------------------------------------------------------
__global__ void conv_silu_kernel(const float* __restrict__ conv_w,
                                 const float* __restrict__ conv_b)
{
    int c = blockIdx.x * 256 + threadIdx.x;
    int m = blockIdx.y;
    int s = m & (Sc - 1);
    int col;
    if (c < 2048)      col = (c >> 7) * 768 + (c & 127);
    else if (c < 4096) { int c2 = c - 2048; col = (c2 >> 7) * 768 + 128 + (c2 & 127); }
    else               { int c3 = c - 4096; col = (c3 >> 8) * 768 + 256 + (c3 & 255); }
    float acc = conv_b[c];
    const float* w = conv_w + c * 4;
#pragma unroll
    for (int j = 0; j < 4; j++) {
        int sp = s - 3 + j;
        if (sp >= 0)
            acc = fmaf(g_qkvz[(size_t)(m - 3 + j) * FQ + col], w[j], acc);
    }
    g_conv[(size_t)m * CDc + c] = acc / (1.f + expf(-acc));
}

__global__ void qknorm_kernel()
{
    int m = blockIdx.x, hk = blockIdx.y, d = threadIdx.x;
    float qv = g_conv[(size_t)m * CDc + hk * 128 + d];
    float kv = g_conv[(size_t)m * CDc + 2048 + hk * 128 + d];
    float sq = qv * qv, sk = kv * kv;
#pragma unroll
    for (int o = 16; o > 0; o >>= 1) {
        sq += __shfl_xor_sync(0xffffffffu, sq, o);
        sk += __shfl_xor_sync(0xffffffffu, sk, o);
    }
    __shared__ float rb[8];
    int w = d >> 5;
    if ((d & 31) == 0) { rb[w] = sq; rb[4 + w] = sk; }
    __syncthreads();
    float sumq = rb[0] + rb[1] + rb[2] + rb[3];
    float sumk = rb[4] + rb[5] + rb[6] + rb[7];
    float rq = rsqrtf(sumq + EPSc) * 0.08838834764831845f;
    float rk = rsqrtf(sumk + EPSc);
    g_qn[m * 2048 + hk * 128 + d] = qv * rq;
    g_kn[m * 2048 + hk * 128 + d] = kv * rk;
}

__global__ void gbeta_kernel(const float* __restrict__ a_log,
                             const float* __restrict__ dt_bias)
{
    int idx = blockIdx.x * 256 + threadIdx.x;
    int m = idx >> 5, hv = idx & 31;
    int hk = hv >> 1, gi = hv & 1;
    float bval = g_ba[m * 64 + hk * 4 + gi];
    float aval = g_ba[m * 64 + hk * 4 + 2 + gi];
    float x = aval + dt_bias[hv];
    float sp = (x > 20.f) ? x : log1pf(expf(x));
    g_gg[idx]   = -expf(a_log[hv]) * sp;
    g_beta[idx] = 1.f / (1.f + expf(-bval));
}

__global__ void __launch_bounds__(256) scan_kernel()
{
    int bh = blockIdx.x;
    int bb = bh >> 5, hv = bh & 31, hk = hv >> 1;
    int t = threadIdx.x;
    int v = t & 127, half = t >> 7, dbase = half * 64;
    float S[64];
#pragma unroll
    for (int i = 0; i < 64; i++) S[i] = 0.f;
    __shared__ float ks[128], qs[128], vs[128];
    __shared__ float predr[2][128], ored[2][128];
    __shared__ float egs, betas;
    int base_qk = hk * 128;
    for (int s = 0; s < Sc; s++) {
        int m = bb * Sc + s;
        if (t < 128) {
            ks[t] = g_kn[m * 2048 + base_qk + t];
            qs[t] = g_qn[m * 2048 + base_qk + t];
            vs[t] = g_conv[(size_t)m * CDc + 4096 + hv * 128 + t];
        }
        if (t == 0) {
            egs   = expf(g_gg[m * 32 + hv]);
            betas = g_beta[m * 32 + hv];
        }
        __syncthreads();
        float eg = egs;
        float pred = 0.f;
#pragma unroll
        for (int d = 0; d < 64; d++) {
            S[d] *= eg;
            pred = fmaf(ks[dbase + d], S[d], pred);
        }
        predr[half][v] = pred;
        __syncthreads();
        float delta = (vs[v] - predr[0][v] - predr[1][v]) * betas;
        float o = 0.f;
#pragma unroll
        for (int d = 0; d < 64; d++) {
            S[d] = fmaf(ks[dbase + d], delta, S[d]);
            o = fmaf(qs[dbase + d], S[d], o);
        }
        ored[half][v] = o;
        __syncthreads();
        if (t < 128)
            g_opre[(size_t)m * 4096 + hv * 128 + t] = ored[0][t] + ored[1][t];
    }
}

__global__ void gate_norm_kernel(const float* __restrict__ norm_w)
{
    int m = blockIdx.x, hv = blockIdx.y, d = threadIdx.x;
    int hk = hv >> 1, gi = hv & 1;
    float z = g_qkvz[(size_t)m * FQ + hk * 768 + 512 + gi * 128 + d];
    float o = g_opre[(size_t)m * 4096 + hv * 128 + d] * (z / (1.f + expf(-z)));
    float ss = o * o;
#pragma unroll
    for (int off = 16; off > 0; off >>= 1) ss += __shfl_xor_sync(0xffffffffu, ss, off);
    __shared__ float rb[4];
    if ((d & 31) == 0) rb[d >> 5] = ss;
    __syncthreads();
    float sum = rb[0] + rb[1] + rb[2] + rb[3];
    float rs = rsqrtf(sum * (1.f / 128.f) + EPSc);
    g_ofin[(size_t)m * 4096 + hv * 128 + d] = o * rs * norm_w[d];
}

// ---------------------------------------------------------------------------
extern "C" void kernel_launch(void* const* d_in, const int* in_sizes, int n_in,
                              void* d_out, int out_size)
{
    const float* x       = (const float*)d_in[0];
    const float* w_qkvz  = (const float*)d_in[1];
    const float* w_ba    = (const float*)d_in[2];
    const float* a_log   = (const float*)d_in[3];
    const float* dt_bias = (const float*)d_in[4];
    const float* conv_w  = (const float*)d_in[5];
    const float* conv_b  = (const float*)d_in[6];
    const float* norm_w  = (const float*)d_in[7];
    const float* w_o     = (const float*)d_in[8];
    float* out = (float*)d_out;

    float *p_qkvz, *p_ba, *p_ofin;
    __nv_bfloat16 *p_xhi, *p_xlo, *p_bqhi, *p_bqlo, *p_bohi, *p_bolo, *p_ohi, *p_olo;
    cudaGetSymbolAddress((void**)&p_qkvz, g_qkvz);
    cudaGetSymbolAddress((void**)&p_ba,   g_ba);
    cudaGetSymbolAddress((void**)&p_ofin, g_ofin);
    cudaGetSymbolAddress((void**)&p_xhi,  g_xhi);
    cudaGetSymbolAddress((void**)&p_xlo,  g_xlo);
    cudaGetSymbolAddress((void**)&p_bqhi, g_bqhi);
    cudaGetSymbolAddress((void**)&p_bqlo, g_bqlo);
    cudaGetSymbolAddress((void**)&p_bohi, g_bohi);
    cudaGetSymbolAddress((void**)&p_bolo, g_bolo);
    cudaGetSymbolAddress((void**)&p_ohi,  g_ohi);
    cudaGetSymbolAddress((void**)&p_olo,  g_olo);

    // prep: splits + weight transposes
    split_kernel<<<(Mtot * Hc) / 256, 256>>>(x, p_xhi, p_xlo);
    transpose_split_kernel<<<dim3(FQ / 32, Hc / 32), dim3(32, 8)>>>(w_qkvz, p_bqhi, p_bqlo, Hc, FQ);
    transpose_split_kernel<<<dim3(Hc / 32, 4096 / 32), dim3(32, 8)>>>(w_o, p_bohi, p_bolo, 4096, Hc);

    // K1: qkvz = x @ w_qkvz (tensor cores, 3-plane bf16 split)
    mma_gemm_kernel<<<dim3(FQ / 128, Mtot / 128), 256>>>(
        p_xhi, p_xlo, p_bqhi, p_bqlo, p_qkvz, Hc, FQ);
    // K2: ba = x @ w_ba
    sgemm_kernel<true><<<dim3(1, Mtot / 128), 256>>>(x, w_ba, p_ba, Mtot, 64, Hc);
    // K3: conv + silu
    conv_silu_kernel<<<dim3(CDc / 256, Mtot), 256>>>(conv_w, conv_b);
    // K4: q/k l2norm
    qknorm_kernel<<<dim3(Mtot, HKc), 128>>>();
    // K5: gates
    gbeta_kernel<<<(Mtot * HVc) / 256, 256>>>(a_log, dt_bias);
    // K6: recurrent scan
    scan_kernel<<<2 * HVc, 256>>>();
    // K7: gate + rmsnorm, then split o
    gate_norm_kernel<<<dim3(Mtot, HVc), 128>>>(norm_w);
    split_kernel<<<(Mtot * 4096) / 256, 256>>>(p_ofin, p_ohi, p_olo);
    // K8: out = o @ w_o (tensor cores)
    mma_gemm_kernel<<<dim3(Hc / 128, Mtot / 128), 256>>>(
        p_ohi, p_olo, p_bohi, p_bolo, out, 4096, Hc);
}

// round 4
// speedup vs baseline: 1.9472x; 1.3340x over previous
#include <cuda_runtime.h>
#include <cuda_bf16.h>
#include <math.h>
#include <stdint.h>

// ---------------------------------------------------------------------------
// GatedDeltaNet  B=2 S=2048 H=2048 HK=16 HV=32 DK=DV=128 G=2 K=4
// Round 4:
//  - fused 3-plane bf16-split mma.sync GEMM (one pass over tiles, all three
//    plane MMAs per load: Ah*Bh + Ah*Bl + Al*Bh into one accumulator)
//  - scan split to 128 blocks (2 per head), 32 state elems/thread, ILP-2
//  - gate_norm writes bf16 hi/lo directly (no separate split pass)
// ---------------------------------------------------------------------------

#define Sc    2048
#define Hc    2048
#define HKc   16
#define HVc   32
#define CDc   8192
#define FQ    12288
#define Mtot  4096
#define EPSc  1e-6f

// ------------------------------ scratch ------------------------------------
__device__ float g_qkvz[(size_t)Mtot * FQ];
__device__ float g_ba[Mtot * 64];
__device__ float g_conv[(size_t)Mtot * CDc];
__device__ float g_qn[Mtot * 2048];
__device__ float g_kn[Mtot * 2048];
__device__ float g_gg[Mtot * HVc];
__device__ float g_beta[Mtot * HVc];
__device__ float g_opre[(size_t)Mtot * 4096];

__device__ __nv_bfloat16 g_xhi[(size_t)Mtot * Hc];
__device__ __nv_bfloat16 g_xlo[(size_t)Mtot * Hc];
__device__ __nv_bfloat16 g_bqhi[(size_t)FQ * Hc];     // w_qkvz^T [12288,2048]
__device__ __nv_bfloat16 g_bqlo[(size_t)FQ * Hc];
__device__ __nv_bfloat16 g_bohi[(size_t)Hc * 4096];   // w_o^T   [2048,4096]
__device__ __nv_bfloat16 g_bolo[(size_t)Hc * 4096];
__device__ __nv_bfloat16 g_ohi[(size_t)Mtot * 4096];
__device__ __nv_bfloat16 g_olo[(size_t)Mtot * 4096];

// ------------------------------ helpers ------------------------------------
__device__ __forceinline__ uint32_t smem_u32(const void* p) {
    uint32_t a;
    asm("{ .reg .u64 t; cvta.to.shared.u64 t, %1; cvt.u32.u64 %0, t; }"
        : "=r"(a) : "l"(p));
    return a;
}
__device__ __forceinline__ void cp_async16(uint32_t saddr, const void* gaddr) {
    asm volatile("cp.async.cg.shared.global [%0], [%1], 16;"
                 :: "r"(saddr), "l"(gaddr) : "memory");
}
__device__ __forceinline__ void cp_commit() {
    asm volatile("cp.async.commit_group;" ::: "memory");
}
template <int N>
__device__ __forceinline__ void cp_wait() {
    asm volatile("cp.async.wait_group %0;" :: "n"(N) : "memory");
}
__device__ __forceinline__ void mma16816(float* c, const uint32_t* a, const uint32_t* b) {
    asm volatile(
        "mma.sync.aligned.m16n8k16.row.col.f32.bf16.bf16.f32 "
        "{%0,%1,%2,%3}, {%4,%5,%6,%7}, {%8,%9}, {%0,%1,%2,%3};"
        : "+f"(c[0]), "+f"(c[1]), "+f"(c[2]), "+f"(c[3])
        : "r"(a[0]), "r"(a[1]), "r"(a[2]), "r"(a[3]), "r"(b[0]), "r"(b[1]));
}

// ---------------------------------------------------------------------------
// fused 3-plane split-bf16 GEMM: C = Ah*Bh^T + Ah*Bl^T + Al*Bh^T
// block tile 128x128, 8 warps (4M x 2N), warp tile 32x64, K chunk 32,
// cp.async double-buffered; 4 tiles (Ah,Al,Bh,Bl) staged per chunk.
// ---------------------------------------------------------------------------
#define RS 40                 // smem row stride in halves (80B, conflict-free)
#define TILE_H (128 * RS)     // halves per 128x32 tile

__global__ void __launch_bounds__(256, 2) mma_gemm_kernel(
    const __nv_bfloat16* __restrict__ Ah, const __nv_bfloat16* __restrict__ Al,
    const __nv_bfloat16* __restrict__ Bh, const __nv_bfloat16* __restrict__ Bl,
    float* __restrict__ C, int Kd, int N)
{
    extern __shared__ __align__(16) __nv_bfloat16 sm[];
    // stage s in {0,1}; tiles: 0=Ah 1=Al 2=Bh 3=Bl
    const int t = threadIdx.x, lane = t & 31, w = t >> 5;
    const int wm = (w & 3) * 32, wn = (w >> 2) * 64;
    const int grp = lane >> 2, q = lane & 3;
    const int bx = blockIdx.x, by = blockIdx.y;

    const int kiters = Kd >> 5;

    float acc[2][8][4];
#pragma unroll
    for (int mi = 0; mi < 2; mi++)
#pragma unroll
        for (int ni = 0; ni < 8; ni++)
#pragma unroll
            for (int j = 0; j < 4; j++) acc[mi][ni][j] = 0.f;

    // per-thread chunks: 512 uint4 per tile / 256 threads = 2 per tile
    const int c0 = t, c1 = t + 256;
    const int r0 = c0 >> 2, s0 = c0 & 3;
    const int r1 = c1 >> 2, s1 = c1 & 3;

    uint32_t smb = smem_u32(sm);

    auto issue = [&](int stage, int kc) {
        size_t k0 = (size_t)kc << 5;
        const __nv_bfloat16* srcs[4] = {
            Ah + (size_t)(by * 128) * Kd, Al + (size_t)(by * 128) * Kd,
            Bh + (size_t)(bx * 128) * Kd, Bl + (size_t)(bx * 128) * Kd };
#pragma unroll
        for (int ti = 0; ti < 4; ti++) {
            uint32_t base = smb + (uint32_t)((stage * 4 + ti) * TILE_H) * 2;
            cp_async16(base + (r0 * RS + s0 * 8) * 2,
                       srcs[ti] + (size_t)r0 * Kd + k0 + s0 * 8);
            cp_async16(base + (r1 * RS + s1 * 8) * 2,
                       srcs[ti] + (size_t)r1 * Kd + k0 + s1 * 8);
        }
        cp_commit();
    };

    issue(0, 0);

    for (int it = 0; it < kiters; it++) {
        int buf = it & 1;
        if (it + 1 < kiters) { issue(buf ^ 1, it + 1); cp_wait<1>(); }
        else                 { cp_wait<0>(); }
        __syncthreads();

        const __nv_bfloat16* sah = sm + (buf * 4 + 0) * TILE_H;
        const __nv_bfloat16* sal = sm + (buf * 4 + 1) * TILE_H;
        const __nv_bfloat16* sbh = sm + (buf * 4 + 2) * TILE_H;
        const __nv_bfloat16* sbl = sm + (buf * 4 + 3) * TILE_H;

#pragma unroll
        for (int ks = 0; ks < 2; ks++) {
            const int k16 = ks * 16;
            uint32_t ah[2][4], al[2][4];
#pragma unroll
            for (int mi = 0; mi < 2; mi++) {
                int ra = wm + mi * 16 + grp;
                ah[mi][0] = *reinterpret_cast<const uint32_t*>(&sah[ra * RS + k16 + q * 2]);
                ah[mi][1] = *reinterpret_cast<const uint32_t*>(&sah[(ra + 8) * RS + k16 + q * 2]);
                ah[mi][2] = *reinterpret_cast<const uint32_t*>(&sah[ra * RS + k16 + 8 + q * 2]);
                ah[mi][3] = *reinterpret_cast<const uint32_t*>(&sah[(ra + 8) * RS + k16 + 8 + q * 2]);
                al[mi][0] = *reinterpret_cast<const uint32_t*>(&sal[ra * RS + k16 + q * 2]);
                al[mi][1] = *reinterpret_cast<const uint32_t*>(&sal[(ra + 8) * RS + k16 + q * 2]);
                al[mi][2] = *reinterpret_cast<const uint32_t*>(&sal[ra * RS + k16 + 8 + q * 2]);
                al[mi][3] = *reinterpret_cast<const uint32_t*>(&sal[(ra + 8) * RS + k16 + 8 + q * 2]);
            }
#pragma unroll
            for (int ni = 0; ni < 8; ni++) {
                int cb = wn + ni * 8 + grp;
                uint32_t bh[2], bl[2];
                bh[0] = *reinterpret_cast<const uint32_t*>(&sbh[cb * RS + k16 + q * 2]);
                bh[1] = *reinterpret_cast<const uint32_t*>(&sbh[cb * RS + k16 + 8 + q * 2]);
                bl[0] = *reinterpret_cast<const uint32_t*>(&sbl[cb * RS + k16 + q * 2]);
                bl[1] = *reinterpret_cast<const uint32_t*>(&sbl[cb * RS + k16 + 8 + q * 2]);
                mma16816(acc[0][ni], ah[0], bh);
                mma16816(acc[1][ni], ah[1], bh);
                mma16816(acc[0][ni], ah[0], bl);
                mma16816(acc[1][ni], ah[1], bl);
                mma16816(acc[0][ni], al[0], bh);
                mma16816(acc[1][ni], al[1], bh);
            }
        }
        __syncthreads();
    }

    // epilogue
#pragma unroll
    for (int mi = 0; mi < 2; mi++) {
        int row = by * 128 + wm + mi * 16 + grp;
#pragma unroll
        for (int ni = 0; ni < 8; ni++) {
            int col = bx * 128 + wn + ni * 8 + q * 2;
            float2 v0 = make_float2(acc[mi][ni][0], acc[mi][ni][1]);
            float2 v1 = make_float2(acc[mi][ni][2], acc[mi][ni][3]);
            *reinterpret_cast<float2*>(C + (size_t)row * N + col) = v0;
            *reinterpret_cast<float2*>(C + (size_t)(row + 8) * N + col) = v1;
        }
    }
}
#define GEMM_SMEM (2 * 4 * TILE_H * 2)   // 81920 bytes

// ---------------------------------------------------------------------------
__global__ void split_kernel(const float* __restrict__ src,
                             __nv_bfloat16* __restrict__ hi,
                             __nv_bfloat16* __restrict__ lo)
{
    size_t i = (size_t)blockIdx.x * 256 + threadIdx.x;
    float v = src[i];
    __nv_bfloat16 h = __float2bfloat16(v);
    hi[i] = h;
    lo[i] = __float2bfloat16(v - __bfloat162float(h));
}

// transpose + split: W[K,N] fp32 -> Th/Tl[N,K] bf16
__global__ void transpose_split_kernel(const float* __restrict__ W,
                                       __nv_bfloat16* __restrict__ Th,
                                       __nv_bfloat16* __restrict__ Tl,
                                       int K, int N)
{
    __shared__ float tile[32][33];
    int n0 = blockIdx.x * 32, k0 = blockIdx.y * 32;
    int tx = threadIdx.x, ty = threadIdx.y;
#pragma unroll
    for (int j = 0; j < 4; j++)
        tile[ty + j * 8][tx] = W[(size_t)(k0 + ty + j * 8) * N + n0 + tx];
    __syncthreads();
#pragma unroll
    for (int j = 0; j < 4; j++) {
        float v = tile[tx][ty + j * 8];
        __nv_bfloat16 h = __float2bfloat16(v);
        size_t o = (size_t)(n0 + ty + j * 8) * K + k0 + tx;
        Th[o] = h;
        Tl[o] = __float2bfloat16(v - __bfloat162float(h));
    }
}

// ---------------------------------------------------------------------------
// SIMT fp32 GEMM (tiny ba GEMM only)
// ---------------------------------------------------------------------------
template <bool GUARD>
__global__ void __launch_bounds__(256) sgemm_kernel(
    const float* __restrict__ A, const float* __restrict__ Bm,
    float* __restrict__ C, int M, int N, int Kd)
{
    __shared__ float As[8][128];
    __shared__ float Bs[8][128];
    int t = threadIdx.x;
    int bx = blockIdx.x, by = blockIdx.y;
    int tx = t & 15, ty = t >> 4;
    float acc[8][8];
#pragma unroll
    for (int i = 0; i < 8; i++)
#pragma unroll
        for (int j = 0; j < 8; j++) acc[i][j] = 0.f;
    int arow = t >> 1, acol4 = (t & 1) * 4;
    int brow = t >> 5, bcol4 = (t & 31) * 4;
    const float* Aptr = A + (size_t)(by * 128 + arow) * Kd;
    int bcolg = bx * 128 + bcol4;
    for (int k0 = 0; k0 < Kd; k0 += 8) {
        float4 a4 = *reinterpret_cast<const float4*>(Aptr + k0 + acol4);
        As[acol4 + 0][arow] = a4.x; As[acol4 + 1][arow] = a4.y;
        As[acol4 + 2][arow] = a4.z; As[acol4 + 3][arow] = a4.w;
        float4 b4 = make_float4(0.f, 0.f, 0.f, 0.f);
        if (!GUARD || bcolg < N)
            b4 = *reinterpret_cast<const float4*>(Bm + (size_t)(k0 + brow) * N + bcolg);
        *reinterpret_cast<float4*>(&Bs[brow][bcol4]) = b4;
        __syncthreads();
#pragma unroll
        for (int kk = 0; kk < 8; kk++) {
            float a[8], b[8];
            *reinterpret_cast<float4*>(a)     = *reinterpret_cast<const float4*>(&As[kk][ty * 8]);
            *reinterpret_cast<float4*>(a + 4) = *reinterpret_cast<const float4*>(&As[kk][ty * 8 + 4]);
            *reinterpret_cast<float4*>(b)     = *reinterpret_cast<const float4*>(&Bs[kk][tx * 8]);
            *reinterpret_cast<float4*>(b + 4) = *reinterpret_cast<const float4*>(&Bs[kk][tx * 8 + 4]);
#pragma unroll
            for (int i = 0; i < 8; i++)
#pragma unroll
                for (int j = 0; j < 8; j++)
                    acc[i][j] = fmaf(a[i], b[j], acc[i][j]);
        }
        __syncthreads();
    }
#pragma unroll
    for (int i = 0; i < 8; i++) {
        int row = by * 128 + ty * 8 + i;
#pragma unroll
        for (int j = 0; j < 8; j += 4) {
            int col = bx * 128 + tx * 8 + j;
            if (!GUARD || col < N) {
                float4 v4 = make_float4(acc[i][j], acc[i][j + 1], acc[i][j + 2], acc[i][j + 3]);
                *reinterpret_cast<float4*>(C + (size_t)row * N + col) = v4;
            }
        }
    }
}

// ---------------------------------------------------------------------------
__global__ void conv_silu_kernel(const float* __restrict__ conv_w,
                                 const float* __restrict__ conv_b)
{
    int c = blockIdx.x * 256 + threadIdx.x;
    int m = blockIdx.y;
    int s = m & (Sc - 1);
    int col;
    if (c < 2048)      col = (c >> 7) * 768 + (c & 127);
    else if (c < 4096) { int c2 = c - 2048; col = (c2 >> 7) * 768 + 128 + (c2 & 127); }
    else               { int c3 = c - 4096; col = (c3 >> 8) * 768 + 256 + (c3 & 255); }
    float acc = conv_b[c];
    const float* w = conv_w + c * 4;
#pragma unroll
    for (int j = 0; j < 4; j++) {
        int sp = s - 3 + j;
        if (sp >= 0)
            acc = fmaf(g_qkvz[(size_t)(m - 3 + j) * FQ + col], w[j], acc);
    }
    g_conv[(size_t)m * CDc + c] = acc / (1.f + expf(-acc));
}

__global__ void qknorm_kernel()
{
    int m = blockIdx.x, hk = blockIdx.y, d = threadIdx.x;
    float qv = g_conv[(size_t)m * CDc + hk * 128 + d];
    float kv = g_conv[(size_t)m * CDc + 2048 + hk * 128 + d];
    float sq = qv * qv, sk = kv * kv;
#pragma unroll
    for (int o = 16; o > 0; o >>= 1) {
        sq += __shfl_xor_sync(0xffffffffu, sq, o);
        sk += __shfl_xor_sync(0xffffffffu, sk, o);
    }
    __shared__ float rb[8];
    int w = d >> 5;
    if ((d & 31) == 0) { rb[w] = sq; rb[4 + w] = sk; }
    __syncthreads();
    float sumq = rb[0] + rb[1] + rb[2] + rb[3];
    float sumk = rb[4] + rb[5] + rb[6] + rb[7];
    float rq = rsqrtf(sumq + EPSc) * 0.08838834764831845f;
    float rk = rsqrtf(sumk + EPSc);
    g_qn[m * 2048 + hk * 128 + d] = qv * rq;
    g_kn[m * 2048 + hk * 128 + d] = kv * rk;
}

__global__ void gbeta_kernel(const float* __restrict__ a_log,
                             const float* __restrict__ dt_bias)
{
    int idx = blockIdx.x * 256 + threadIdx.x;
    int m = idx >> 5, hv = idx & 31;
    int hk = hv >> 1, gi = hv & 1;
    float bval = g_ba[m * 64 + hk * 4 + gi];
    float aval = g_ba[m * 64 + hk * 4 + 2 + gi];
    float x = aval + dt_bias[hv];
    float sp = (x > 20.f) ? x : log1pf(expf(x));
    g_gg[idx]   = -expf(a_log[hv]) * sp;
    g_beta[idx] = 1.f / (1.f + expf(-bval));
}

// ---------------------------------------------------------------------------
// gated delta scan: 128 blocks = (b, hv, vhalf). 256 threads.
// thread t: column vl = t&63 (within half), row quarter qt = t>>6 (32 rows).
// ---------------------------------------------------------------------------
__global__ void __launch_bounds__(256) scan_kernel()
{
    int bid = blockIdx.x;                 // 0..127
    int bb = bid >> 6;
    int r = bid & 63;
    int hv = r >> 1, half = r & 1, hk = hv >> 1;
    int t = threadIdx.x;
    int vl = t & 63, qt = t >> 6, dbase = qt * 32;

    float S[32];
#pragma unroll
    for (int i = 0; i < 32; i++) S[i] = 0.f;

    __shared__ float ks[128], qs[128], vs[64];
    __shared__ float red[4][64], ored[4][64];
    __shared__ float egs, betas;
    int base_qk = hk * 128;
    int vcol = hv * 128 + half * 64;

    for (int s = 0; s < Sc; s++) {
        int m = bb * Sc + s;
        if (t < 128) {
            ks[t] = g_kn[m * 2048 + base_qk + t];
            qs[t] = g_qn[m * 2048 + base_qk + t];
        } else if (t < 192) {
            vs[t - 128] = g_conv[(size_t)m * CDc + 4096 + vcol + (t - 128)];
        } else if (t == 255) {
            egs   = expf(g_gg[m * 32 + hv]);
            betas = g_beta[m * 32 + hv];
        }
        __syncthreads();

        float eg = egs;
        float p0 = 0.f, p1 = 0.f;
#pragma unroll
        for (int d = 0; d < 32; d += 2) {
            S[d]     *= eg;
            S[d + 1] *= eg;
            p0 = fmaf(ks[dbase + d],     S[d],     p0);
            p1 = fmaf(ks[dbase + d + 1], S[d + 1], p1);
        }
        red[qt][vl] = p0 + p1;
        __syncthreads();

        float delta = (vs[vl] - (red[0][vl] + red[1][vl] + red[2][vl] + red[3][vl])) * betas;
        float o0 = 0.f, o1 = 0.f;
#pragma unroll
        for (int d = 0; d < 32; d += 2) {
            S[d]     = fmaf(ks[dbase + d],     delta, S[d]);
            S[d + 1] = fmaf(ks[dbase + d + 1], delta, S[d + 1]);
            o0 = fmaf(qs[dbase + d],     S[d],     o0);
            o1 = fmaf(qs[dbase + d + 1], S[d + 1], o1);
        }
        ored[qt][vl] = o0 + o1;
        __syncthreads();

        if (t < 64)
            g_opre[(size_t)m * 4096 + vcol + t] =
                ored[0][t] + ored[1][t] + ored[2][t] + ored[3][t];
    }
}

// ---------------------------------------------------------------------------
// o * silu(z), RMSNorm, then split to bf16 hi/lo directly.
// ---------------------------------------------------------------------------
__global__ void gate_norm_kernel(const float* __restrict__ norm_w)
{
    int m = blockIdx.x, hv = blockIdx.y, d = threadIdx.x;
    int hk = hv >> 1, gi = hv & 1;
    float z = g_qkvz[(size_t)m * FQ + hk * 768 + 512 + gi * 128 + d];
    float o = g_opre[(size_t)m * 4096 + hv * 128 + d] * (z / (1.f + expf(-z)));
    float ss = o * o;
#pragma unroll
    for (int off = 16; off > 0; off >>= 1) ss += __shfl_xor_sync(0xffffffffu, ss, off);
    __shared__ float rb[4];
    if ((d & 31) == 0) rb[d >> 5] = ss;
    __syncthreads();
    float sum = rb[0] + rb[1] + rb[2] + rb[3];
    float rs = rsqrtf(sum * (1.f / 128.f) + EPSc);
    float v = o * rs * norm_w[d];
    __nv_bfloat16 h = __float2bfloat16(v);
    size_t idx = (size_t)m * 4096 + hv * 128 + d;
    g_ohi[idx] = h;
    g_olo[idx] = __float2bfloat16(v - __bfloat162float(h));
}

// ---------------------------------------------------------------------------
extern "C" void kernel_launch(void* const* d_in, const int* in_sizes, int n_in,
                              void* d_out, int out_size)
{
    const float* x       = (const float*)d_in[0];
    const float* w_qkvz  = (const float*)d_in[1];
    const float* w_ba    = (const float*)d_in[2];
    const float* a_log   = (const float*)d_in[3];
    const float* dt_bias = (const float*)d_in[4];
    const float* conv_w  = (const float*)d_in[5];
    const float* conv_b  = (const float*)d_in[6];
    const float* norm_w  = (const float*)d_in[7];
    const float* w_o     = (const float*)d_in[8];
    float* out = (float*)d_out;

    float *p_qkvz, *p_ba;
    __nv_bfloat16 *p_xhi, *p_xlo, *p_bqhi, *p_bqlo, *p_bohi, *p_bolo, *p_ohi, *p_olo;
    cudaGetSymbolAddress((void**)&p_qkvz, g_qkvz);
    cudaGetSymbolAddress((void**)&p_ba,   g_ba);
    cudaGetSymbolAddress((void**)&p_xhi,  g_xhi);
    cudaGetSymbolAddress((void**)&p_xlo,  g_xlo);
    cudaGetSymbolAddress((void**)&p_bqhi, g_bqhi);
    cudaGetSymbolAddress((void**)&p_bqlo, g_bqlo);
    cudaGetSymbolAddress((void**)&p_bohi, g_bohi);
    cudaGetSymbolAddress((void**)&p_bolo, g_bolo);
    cudaGetSymbolAddress((void**)&p_ohi,  g_ohi);
    cudaGetSymbolAddress((void**)&p_olo,  g_olo);

    cudaFuncSetAttribute(mma_gemm_kernel,
                         cudaFuncAttributeMaxDynamicSharedMemorySize, GEMM_SMEM);

    // prep: splits + weight transposes
    split_kernel<<<(Mtot * Hc) / 256, 256>>>(x, p_xhi, p_xlo);
    transpose_split_kernel<<<dim3(FQ / 32, Hc / 32), dim3(32, 8)>>>(w_qkvz, p_bqhi, p_bqlo, Hc, FQ);
    transpose_split_kernel<<<dim3(Hc / 32, 4096 / 32), dim3(32, 8)>>>(w_o, p_bohi, p_bolo, 4096, Hc);

    // K1: qkvz = x @ w_qkvz (fused 3-plane tensor-core GEMM)
    mma_gemm_kernel<<<dim3(FQ / 128, Mtot / 128), 256, GEMM_SMEM>>>(
        p_xhi, p_xlo, p_bqhi, p_bqlo, p_qkvz, Hc, FQ);
    // K2: ba = x @ w_ba
    sgemm_kernel<true><<<dim3(1, Mtot / 128), 256>>>(x, w_ba, p_ba, Mtot, 64, Hc);
    // K3: conv + silu
    conv_silu_kernel<<<dim3(CDc / 256, Mtot), 256>>>(conv_w, conv_b);
    // K4: q/k l2norm
    qknorm_kernel<<<dim3(Mtot, HKc), 128>>>();
    // K5: gates
    gbeta_kernel<<<(Mtot * HVc) / 256, 256>>>(a_log, dt_bias);
    // K6: recurrent scan (128 blocks)
    scan_kernel<<<128, 256>>>();
    // K7: gate + rmsnorm + bf16 split
    gate_norm_kernel<<<dim3(Mtot, HVc), 128>>>(norm_w);
    // K8: out = o @ w_o
    mma_gemm_kernel<<<dim3(Hc / 128, Mtot / 128), 256, GEMM_SMEM>>>(
        p_ohi, p_olo, p_bohi, p_bolo, out, 4096, Hc);
}

// round 5
// speedup vs baseline: 2.3869x; 1.2258x over previous
#include <cuda_runtime.h>
#include <cuda_bf16.h>
#include <math.h>
#include <stdint.h>

// ---------------------------------------------------------------------------
// GatedDeltaNet  B=2 S=2048 H=2048 HK=16 HV=32 DK=DV=128 G=2 K=4
// Round 5:
//  - scan: cp.async double-buffered prefetch of next step's k/q/v/g/beta
//    (hides per-step memory latency behind compute; was barrier-serialized)
//  - GEMM: ldmatrix.x4 fragment loads (12 LDSM vs ~96 LDS.32 per k-chunk)
// ---------------------------------------------------------------------------

#define Sc    2048
#define Hc    2048
#define HKc   16
#define HVc   32
#define CDc   8192
#define FQ    12288
#define Mtot  4096
#define EPSc  1e-6f

// ------------------------------ scratch ------------------------------------
__device__ float g_qkvz[(size_t)Mtot * FQ];
__device__ float g_ba[Mtot * 64];
__device__ float g_conv[(size_t)Mtot * CDc];
__device__ float g_qn[Mtot * 2048];
__device__ float g_kn[Mtot * 2048];
__device__ float g_gg[Mtot * HVc];
__device__ float g_beta[Mtot * HVc];
__device__ float g_opre[(size_t)Mtot * 4096];

__device__ __nv_bfloat16 g_xhi[(size_t)Mtot * Hc];
__device__ __nv_bfloat16 g_xlo[(size_t)Mtot * Hc];
__device__ __nv_bfloat16 g_bqhi[(size_t)FQ * Hc];
__device__ __nv_bfloat16 g_bqlo[(size_t)FQ * Hc];
__device__ __nv_bfloat16 g_bohi[(size_t)Hc * 4096];
__device__ __nv_bfloat16 g_bolo[(size_t)Hc * 4096];
__device__ __nv_bfloat16 g_ohi[(size_t)Mtot * 4096];
__device__ __nv_bfloat16 g_olo[(size_t)Mtot * 4096];

// ------------------------------ helpers ------------------------------------
__device__ __forceinline__ uint32_t smem_u32(const void* p) {
    uint32_t a;
    asm("{ .reg .u64 t; cvta.to.shared.u64 t, %1; cvt.u32.u64 %0, t; }"
        : "=r"(a) : "l"(p));
    return a;
}
__device__ __forceinline__ void cp_async16(uint32_t saddr, const void* gaddr) {
    asm volatile("cp.async.cg.shared.global [%0], [%1], 16;"
                 :: "r"(saddr), "l"(gaddr) : "memory");
}
__device__ __forceinline__ void cp_async4(uint32_t saddr, const void* gaddr) {
    asm volatile("cp.async.ca.shared.global [%0], [%1], 4;"
                 :: "r"(saddr), "l"(gaddr) : "memory");
}
__device__ __forceinline__ void cp_commit() {
    asm volatile("cp.async.commit_group;" ::: "memory");
}
template <int N>
__device__ __forceinline__ void cp_wait() {
    asm volatile("cp.async.wait_group %0;" :: "n"(N) : "memory");
}
__device__ __forceinline__ void mma16816(float* c, const uint32_t* a, const uint32_t* b) {
    asm volatile(
        "mma.sync.aligned.m16n8k16.row.col.f32.bf16.bf16.f32 "
        "{%0,%1,%2,%3}, {%4,%5,%6,%7}, {%8,%9}, {%0,%1,%2,%3};"
        : "+f"(c[0]), "+f"(c[1]), "+f"(c[2]), "+f"(c[3])
        : "r"(a[0]), "r"(a[1]), "r"(a[2]), "r"(a[3]), "r"(b[0]), "r"(b[1]));
}
__device__ __forceinline__ void ldsm4(uint32_t* r, uint32_t addr) {
    asm volatile("ldmatrix.sync.aligned.m8n8.x4.shared.b16 {%0,%1,%2,%3}, [%4];"
                 : "=r"(r[0]), "=r"(r[1]), "=r"(r[2]), "=r"(r[3]) : "r"(addr));
}

// ---------------------------------------------------------------------------
// fused 3-plane split-bf16 GEMM: C = Ah*Bh^T + Ah*Bl^T + Al*Bh^T
// block tile 128x128, 8 warps (4M x 2N), warp tile 32x64, K chunk 32,
// cp.async double-buffered; ldmatrix fragment loads.
// ---------------------------------------------------------------------------
#define RS 40                 // smem row stride in halves (80B, conflict-free)
#define TILE_H (128 * RS)     // halves per 128x32 tile

__global__ void __launch_bounds__(256, 2) mma_gemm_kernel(
    const __nv_bfloat16* __restrict__ Ah, const __nv_bfloat16* __restrict__ Al,
    const __nv_bfloat16* __restrict__ Bh, const __nv_bfloat16* __restrict__ Bl,
    float* __restrict__ C, int Kd, int N)
{
    extern __shared__ __align__(16) __nv_bfloat16 sm[];
    const int t = threadIdx.x, lane = t & 31, w = t >> 5;
    const int wm = (w & 3) * 32, wn = (w >> 2) * 64;
    const int grp = lane >> 2, q = lane & 3;
    const int bx = blockIdx.x, by = blockIdx.y;

    const int kiters = Kd >> 5;

    float acc[2][8][4];
#pragma unroll
    for (int mi = 0; mi < 2; mi++)
#pragma unroll
        for (int ni = 0; ni < 8; ni++)
#pragma unroll
            for (int j = 0; j < 4; j++) acc[mi][ni][j] = 0.f;

    const int c0 = t, c1 = t + 256;
    const int r0 = c0 >> 2, s0 = c0 & 3;
    const int r1 = c1 >> 2, s1 = c1 & 3;

    uint32_t smb = smem_u32(sm);

    auto issue = [&](int stage, int kc) {
        size_t k0 = (size_t)kc << 5;
        const __nv_bfloat16* srcs[4] = {
            Ah + (size_t)(by * 128) * Kd, Al + (size_t)(by * 128) * Kd,
            Bh + (size_t)(bx * 128) * Kd, Bl + (size_t)(bx * 128) * Kd };
#pragma unroll
        for (int ti = 0; ti < 4; ti++) {
            uint32_t base = smb + (uint32_t)((stage * 4 + ti) * TILE_H) * 2;
            cp_async16(base + (r0 * RS + s0 * 8) * 2,
                       srcs[ti] + (size_t)r0 * Kd + k0 + s0 * 8);
            cp_async16(base + (r1 * RS + s1 * 8) * 2,
                       srcs[ti] + (size_t)r1 * Kd + k0 + s1 * 8);
        }
        cp_commit();
    };

    issue(0, 0);

    // ldmatrix lane->address components
    const int r8  = lane & 7;
    const int hm  = (lane >> 3) & 1;   // A: row half / B: k half
    const int hk2 = (lane >> 4) & 1;   // A: k half  / B: n-octet select

    for (int it = 0; it < kiters; it++) {
        int buf = it & 1;
        if (it + 1 < kiters) { issue(buf ^ 1, it + 1); cp_wait<1>(); }
        else                 { cp_wait<0>(); }
        __syncthreads();

        uint32_t sahb = smb + (uint32_t)((buf * 4 + 0) * TILE_H) * 2;
        uint32_t salb = smb + (uint32_t)((buf * 4 + 1) * TILE_H) * 2;
        uint32_t sbhb = smb + (uint32_t)((buf * 4 + 2) * TILE_H) * 2;
        uint32_t sblb = smb + (uint32_t)((buf * 4 + 3) * TILE_H) * 2;

#pragma unroll
        for (int ks = 0; ks < 2; ks++) {
            const int k16 = ks * 16;
            uint32_t ah[2][4], al[2][4];
            uint32_t aoff0 = (uint32_t)((wm + hm * 8 + r8) * RS + k16 + hk2 * 8) * 2;
            uint32_t aoff1 = aoff0 + 16 * RS * 2;
            ldsm4(ah[0], sahb + aoff0);
            ldsm4(ah[1], sahb + aoff1);
            ldsm4(al[0], salb + aoff0);
            ldsm4(al[1], salb + aoff1);
#pragma unroll
            for (int pi = 0; pi < 4; pi++) {
                uint32_t boff = (uint32_t)((wn + pi * 16 + hk2 * 8 + r8) * RS + k16 + hm * 8) * 2;
                uint32_t bh4[4], bl4[4];
                ldsm4(bh4, sbhb + boff);
                ldsm4(bl4, sblb + boff);
#pragma unroll
                for (int sub = 0; sub < 2; sub++) {
                    int ni = pi * 2 + sub;
                    mma16816(acc[0][ni], ah[0], bh4 + sub * 2);
                    mma16816(acc[1][ni], ah[1], bh4 + sub * 2);
                    mma16816(acc[0][ni], ah[0], bl4 + sub * 2);
                    mma16816(acc[1][ni], ah[1], bl4 + sub * 2);
                    mma16816(acc[0][ni], al[0], bh4 + sub * 2);
                    mma16816(acc[1][ni], al[1], bh4 + sub * 2);
                }
            }
        }
        __syncthreads();
    }

    // epilogue
#pragma unroll
    for (int mi = 0; mi < 2; mi++) {
        int row = by * 128 + wm + mi * 16 + grp;
#pragma unroll
        for (int ni = 0; ni < 8; ni++) {
            int col = bx * 128 + wn + ni * 8 + q * 2;
            float2 v0 = make_float2(acc[mi][ni][0], acc[mi][ni][1]);
            float2 v1 = make_float2(acc[mi][ni][2], acc[mi][ni][3]);
            *reinterpret_cast<float2*>(C + (size_t)row * N + col) = v0;
            *reinterpret_cast<float2*>(C + (size_t)(row + 8) * N + col) = v1;
        }
    }
}
#define GEMM_SMEM (2 * 4 * TILE_H * 2)   // 81920 bytes

// ---------------------------------------------------------------------------
__global__ void split_kernel(const float* __restrict__ src,
                             __nv_bfloat16* __restrict__ hi,
                             __nv_bfloat16* __restrict__ lo)
{
    size_t i = (size_t)blockIdx.x * 256 + threadIdx.x;
    float v = src[i];
    __nv_bfloat16 h = __float2bfloat16(v);
    hi[i] = h;
    lo[i] = __float2bfloat16(v - __bfloat162float(h));
}

__global__ void transpose_split_kernel(const float* __restrict__ W,
                                       __nv_bfloat16* __restrict__ Th,
                                       __nv_bfloat16* __restrict__ Tl,
                                       int K, int N)
{
    __shared__ float tile[32][33];
    int n0 = blockIdx.x * 32, k0 = blockIdx.y * 32;
    int tx = threadIdx.x, ty = threadIdx.y;
#pragma unroll
    for (int j = 0; j < 4; j++)
        tile[ty + j * 8][tx] = W[(size_t)(k0 + ty + j * 8) * N + n0 + tx];
    __syncthreads();
#pragma unroll
    for (int j = 0; j < 4; j++) {
        float v = tile[tx][ty + j * 8];
        __nv_bfloat16 h = __float2bfloat16(v);
        size_t o = (size_t)(n0 + ty + j * 8) * K + k0 + tx;
        Th[o] = h;
        Tl[o] = __float2bfloat16(v - __bfloat162float(h));
    }
}

// ---------------------------------------------------------------------------
template <bool GUARD>
__global__ void __launch_bounds__(256) sgemm_kernel(
    const float* __restrict__ A, const float* __restrict__ Bm,
    float* __restrict__ C, int M, int N, int Kd)
{
    __shared__ float As[8][128];
    __shared__ float Bs[8][128];
    int t = threadIdx.x;
    int bx = blockIdx.x, by = blockIdx.y;
    int tx = t & 15, ty = t >> 4;
    float acc[8][8];
#pragma unroll
    for (int i = 0; i < 8; i++)
#pragma unroll
        for (int j = 0; j < 8; j++) acc[i][j] = 0.f;
    int arow = t >> 1, acol4 = (t & 1) * 4;
    int brow = t >> 5, bcol4 = (t & 31) * 4;
    const float* Aptr = A + (size_t)(by * 128 + arow) * Kd;
    int bcolg = bx * 128 + bcol4;
    for (int k0 = 0; k0 < Kd; k0 += 8) {
        float4 a4 = *reinterpret_cast<const float4*>(Aptr + k0 + acol4);
        As[acol4 + 0][arow] = a4.x; As[acol4 + 1][arow] = a4.y;
        As[acol4 + 2][arow] = a4.z; As[acol4 + 3][arow] = a4.w;
        float4 b4 = make_float4(0.f, 0.f, 0.f, 0.f);
        if (!GUARD || bcolg < N)
            b4 = *reinterpret_cast<const float4*>(Bm + (size_t)(k0 + brow) * N + bcolg);
        *reinterpret_cast<float4*>(&Bs[brow][bcol4]) = b4;
        __syncthreads();
#pragma unroll
        for (int kk = 0; kk < 8; kk++) {
            float a[8], b[8];
            *reinterpret_cast<float4*>(a)     = *reinterpret_cast<const float4*>(&As[kk][ty * 8]);
            *reinterpret_cast<float4*>(a + 4) = *reinterpret_cast<const float4*>(&As[kk][ty * 8 + 4]);
            *reinterpret_cast<float4*>(b)     = *reinterpret_cast<const float4*>(&Bs[kk][tx * 8]);
            *reinterpret_cast<float4*>(b + 4) = *reinterpret_cast<const float4*>(&Bs[kk][tx * 8 + 4]);
#pragma unroll
            for (int i = 0; i < 8; i++)
#pragma unroll
                for (int j = 0; j < 8; j++)
                    acc[i][j] = fmaf(a[i], b[j], acc[i][j]);
        }
        __syncthreads();
    }
#pragma unroll
    for (int i = 0; i < 8; i++) {
        int row = by * 128 + ty * 8 + i;
#pragma unroll
        for (int j = 0; j < 8; j += 4) {
            int col = bx * 128 + tx * 8 + j;
            if (!GUARD || col < N) {
                float4 v4 = make_float4(acc[i][j], acc[i][j + 1], acc[i][j + 2], acc[i][j + 3]);
                *reinterpret_cast<float4*>(C + (size_t)row * N + col) = v4;
            }
        }
    }
}

// ---------------------------------------------------------------------------
__global__ void conv_silu_kernel(const float* __restrict__ conv_w,
                                 const float* __restrict__ conv_b)
{
    int c = blockIdx.x * 256 + threadIdx.x;
    int m = blockIdx.y;
    int s = m & (Sc - 1);
    int col;
    if (c < 2048)      col = (c >> 7) * 768 + (c & 127);
    else if (c < 4096) { int c2 = c - 2048; col = (c2 >> 7) * 768 + 128 + (c2 & 127); }
    else               { int c3 = c - 4096; col = (c3 >> 8) * 768 + 256 + (c3 & 255); }
    float acc = conv_b[c];
    const float* w = conv_w + c * 4;
#pragma unroll
    for (int j = 0; j < 4; j++) {
        int sp = s - 3 + j;
        if (sp >= 0)
            acc = fmaf(g_qkvz[(size_t)(m - 3 + j) * FQ + col], w[j], acc);
    }
    g_conv[(size_t)m * CDc + c] = acc / (1.f + expf(-acc));
}

__global__ void qknorm_kernel()
{
    int m = blockIdx.x, hk = blockIdx.y, d = threadIdx.x;
    float qv = g_conv[(size_t)m * CDc + hk * 128 + d];
    float kv = g_conv[(size_t)m * CDc + 2048 + hk * 128 + d];
    float sq = qv * qv, sk = kv * kv;
#pragma unroll
    for (int o = 16; o > 0; o >>= 1) {
        sq += __shfl_xor_sync(0xffffffffu, sq, o);
        sk += __shfl_xor_sync(0xffffffffu, sk, o);
    }
    __shared__ float rb[8];
    int w = d >> 5;
    if ((d & 31) == 0) { rb[w] = sq; rb[4 + w] = sk; }
    __syncthreads();
    float sumq = rb[0] + rb[1] + rb[2] + rb[3];
    float sumk = rb[4] + rb[5] + rb[6] + rb[7];
    float rq = rsqrtf(sumq + EPSc) * 0.08838834764831845f;
    float rk = rsqrtf(sumk + EPSc);
    g_qn[m * 2048 + hk * 128 + d] = qv * rq;
    g_kn[m * 2048 + hk * 128 + d] = kv * rk;
}

__global__ void gbeta_kernel(const float* __restrict__ a_log,
                             const float* __restrict__ dt_bias)
{
    int idx = blockIdx.x * 256 + threadIdx.x;
    int m = idx >> 5, hv = idx & 31;
    int hk = hv >> 1, gi = hv & 1;
    float bval = g_ba[m * 64 + hk * 4 + gi];
    float aval = g_ba[m * 64 + hk * 4 + 2 + gi];
    float x = aval + dt_bias[hv];
    float sp = (x > 20.f) ? x : log1pf(expf(x));
    g_gg[idx]   = -expf(a_log[hv]) * sp;
    g_beta[idx] = 1.f / (1.f + expf(-bval));
}

// ---------------------------------------------------------------------------
// gated delta scan, cp.async prefetch pipelined. 128 blocks = (b,hv,vhalf).
// ---------------------------------------------------------------------------
__global__ void __launch_bounds__(256) scan_kernel()
{
    int bid = blockIdx.x;
    int bb = bid >> 6;
    int r = bid & 63;
    int hv = r >> 1, half = r & 1, hk = hv >> 1;
    int t = threadIdx.x;
    int vl = t & 63, qt = t >> 6, dbase = qt * 32;

    float S[32];
#pragma unroll
    for (int i = 0; i < 32; i++) S[i] = 0.f;

    __shared__ __align__(16) float kq[2][256];   // [0:128)=k, [128:256)=q
    __shared__ __align__(16) float vsb[2][64];
    __shared__ float gbb[2][2];                   // [0]=g raw, [1]=beta
    __shared__ float red[4][64], ored[4][64];

    const uint32_t skq = smem_u32(kq);
    const uint32_t svs = smem_u32(vsb);
    const uint32_t sgb = smem_u32(gbb);

    const float* kbase = g_kn + hk * 128;
    const float* qbase = g_qn + hk * 128;
    const float* vbase = g_conv + 4096 + hv * 128 + half * 64;
    const float* gbase = g_gg + hv;
    const float* bbase = g_beta + hv;

    auto prefetch = [&](int buf, int s) {
        int m = bb * Sc + s;
        if (t < 32)
            cp_async16(skq + buf * 1024 + t * 16, kbase + (size_t)m * 2048 + t * 4);
        else if (t < 64)
            cp_async16(skq + buf * 1024 + 512 + (t - 32) * 16,
                       qbase + (size_t)m * 2048 + (t - 32) * 4);
        else if (t < 80)
            cp_async16(svs + buf * 256 + (t - 64) * 16,
                       vbase + (size_t)m * CDc + (t - 64) * 4);
        else if (t == 80)
            cp_async4(sgb + buf * 8, gbase + m * 32);
        else if (t == 81)
            cp_async4(sgb + buf * 8 + 4, bbase + m * 32);
    };

    prefetch(0, 0);
    cp_commit();

    for (int s = 0; s < Sc; s++) {
        int buf = s & 1;
        cp_wait<0>();
        __syncthreads();                     // buffer ready; prior ored reads done
        if (s + 1 < Sc) { prefetch(buf ^ 1, s + 1); cp_commit(); }

        float eg   = expf(gbb[buf][0]);
        float beta = gbb[buf][1];
        const float* ks = kq[buf];
        const float* qs = kq[buf] + 128;
        const float* vs = vsb[buf];

        float p0 = 0.f, p1 = 0.f;
#pragma unroll
        for (int d = 0; d < 32; d += 2) {
            S[d]     *= eg;
            S[d + 1] *= eg;
            p0 = fmaf(ks[dbase + d],     S[d],     p0);
            p1 = fmaf(ks[dbase + d + 1], S[d + 1], p1);
        }
        red[qt][vl] = p0 + p1;
        __syncthreads();

        float delta = (vs[vl] - (red[0][vl] + red[1][vl] + red[2][vl] + red[3][vl])) * beta;
        float o0 = 0.f, o1 = 0.f;
#pragma unroll
        for (int d = 0; d < 32; d += 2) {
            S[d]     = fmaf(ks[dbase + d],     delta, S[d]);
            S[d + 1] = fmaf(ks[dbase + d + 1], delta, S[d + 1]);
            o0 = fmaf(qs[dbase + d],     S[d],     o0);
            o1 = fmaf(qs[dbase + d + 1], S[d + 1], o1);
        }
        ored[qt][vl] = o0 + o1;
        __syncthreads();

        if (t < 64) {
            int m = bb * Sc + s;
            g_opre[(size_t)m * 4096 + hv * 128 + half * 64 + t] =
                ored[0][t] + ored[1][t] + ored[2][t] + ored[3][t];
        }
    }
}

// ---------------------------------------------------------------------------
__global__ void gate_norm_kernel(const float* __restrict__ norm_w)
{
    int m = blockIdx.x, hv = blockIdx.y, d = threadIdx.x;
    int hk = hv >> 1, gi = hv & 1;
    float z = g_qkvz[(size_t)m * FQ + hk * 768 + 512 + gi * 128 + d];
    float o = g_opre[(size_t)m * 4096 + hv * 128 + d] * (z / (1.f + expf(-z)));
    float ss = o * o;
#pragma unroll
    for (int off = 16; off > 0; off >>= 1) ss += __shfl_xor_sync(0xffffffffu, ss, off);
    __shared__ float rb[4];
    if ((d & 31) == 0) rb[d >> 5] = ss;
    __syncthreads();
    float sum = rb[0] + rb[1] + rb[2] + rb[3];
    float rs = rsqrtf(sum * (1.f / 128.f) + EPSc);
    float v = o * rs * norm_w[d];
    __nv_bfloat16 h = __float2bfloat16(v);
    size_t idx = (size_t)m * 4096 + hv * 128 + d;
    g_ohi[idx] = h;
    g_olo[idx] = __float2bfloat16(v - __bfloat162float(h));
}

// ---------------------------------------------------------------------------
extern "C" void kernel_launch(void* const* d_in, const int* in_sizes, int n_in,
                              void* d_out, int out_size)
{
    const float* x       = (const float*)d_in[0];
    const float* w_qkvz  = (const float*)d_in[1];
    const float* w_ba    = (const float*)d_in[2];
    const float* a_log   = (const float*)d_in[3];
    const float* dt_bias = (const float*)d_in[4];
    const float* conv_w  = (const float*)d_in[5];
    const float* conv_b  = (const float*)d_in[6];
    const float* norm_w  = (const float*)d_in[7];
    const float* w_o     = (const float*)d_in[8];
    float* out = (float*)d_out;

    float *p_qkvz, *p_ba;
    __nv_bfloat16 *p_xhi, *p_xlo, *p_bqhi, *p_bqlo, *p_bohi, *p_bolo, *p_ohi, *p_olo;
    cudaGetSymbolAddress((void**)&p_qkvz, g_qkvz);
    cudaGetSymbolAddress((void**)&p_ba,   g_ba);
    cudaGetSymbolAddress((void**)&p_xhi,  g_xhi);
    cudaGetSymbolAddress((void**)&p_xlo,  g_xlo);
    cudaGetSymbolAddress((void**)&p_bqhi, g_bqhi);
    cudaGetSymbolAddress((void**)&p_bqlo, g_bqlo);
    cudaGetSymbolAddress((void**)&p_bohi, g_bohi);
    cudaGetSymbolAddress((void**)&p_bolo, g_bolo);
    cudaGetSymbolAddress((void**)&p_ohi,  g_ohi);
    cudaGetSymbolAddress((void**)&p_olo,  g_olo);

    cudaFuncSetAttribute(mma_gemm_kernel,
                         cudaFuncAttributeMaxDynamicSharedMemorySize, GEMM_SMEM);

    split_kernel<<<(Mtot * Hc) / 256, 256>>>(x, p_xhi, p_xlo);
    transpose_split_kernel<<<dim3(FQ / 32, Hc / 32), dim3(32, 8)>>>(w_qkvz, p_bqhi, p_bqlo, Hc, FQ);
    transpose_split_kernel<<<dim3(Hc / 32, 4096 / 32), dim3(32, 8)>>>(w_o, p_bohi, p_bolo, 4096, Hc);

    mma_gemm_kernel<<<dim3(FQ / 128, Mtot / 128), 256, GEMM_SMEM>>>(
        p_xhi, p_xlo, p_bqhi, p_bqlo, p_qkvz, Hc, FQ);
    sgemm_kernel<true><<<dim3(1, Mtot / 128), 256>>>(x, w_ba, p_ba, Mtot, 64, Hc);
    conv_silu_kernel<<<dim3(CDc / 256, Mtot), 256>>>(conv_w, conv_b);
    qknorm_kernel<<<dim3(Mtot, HKc), 128>>>();
    gbeta_kernel<<<(Mtot * HVc) / 256, 256>>>(a_log, dt_bias);
    scan_kernel<<<128, 256>>>();
    gate_norm_kernel<<<dim3(Mtot, HVc), 128>>>(norm_w);
    mma_gemm_kernel<<<dim3(Hc / 128, Mtot / 128), 256, GEMM_SMEM>>>(
        p_ohi, p_olo, p_bohi, p_bolo, out, 4096, Hc);
}

// round 6
// speedup vs baseline: 2.4453x; 1.0245x over previous
#include <cuda_runtime.h>
#include <cuda_bf16.h>
#include <math.h>
#include <stdint.h>

// ---------------------------------------------------------------------------
// GatedDeltaNet  B=2 S=2048 H=2048 HK=16 HV=32 DK=DV=128 G=2 K=4
// Round 6:
//  - GEMM: k-chunk 64, N-tile 64 (RS=72 pad), 2 CTAs/SM, ldmatrix, cp.async x2
//  - ba GEMM: split-K x8 with deterministic partial buffers + reduce
//  - scan: 2 barriers/step (output store folded into next step's window)
//  - conv_silu + qknorm fused into one kernel
// ---------------------------------------------------------------------------

#define Sc    2048
#define Hc    2048
#define HKc   16
#define HVc   32
#define CDc   8192
#define FQ    12288
#define Mtot  4096
#define EPSc  1e-6f

// ------------------------------ scratch ------------------------------------
__device__ float g_qkvz[(size_t)Mtot * FQ];
__device__ float g_ba[Mtot * 64];
__device__ float g_bapart[8 * Mtot * 64];
__device__ float g_conv[(size_t)Mtot * CDc];
__device__ float g_qn[Mtot * 2048];
__device__ float g_kn[Mtot * 2048];
__device__ float g_gg[Mtot * HVc];
__device__ float g_beta[Mtot * HVc];
__device__ float g_opre[(size_t)Mtot * 4096];

__device__ __nv_bfloat16 g_xhi[(size_t)Mtot * Hc];
__device__ __nv_bfloat16 g_xlo[(size_t)Mtot * Hc];
__device__ __nv_bfloat16 g_bqhi[(size_t)FQ * Hc];
__device__ __nv_bfloat16 g_bqlo[(size_t)FQ * Hc];
__device__ __nv_bfloat16 g_bohi[(size_t)Hc * 4096];
__device__ __nv_bfloat16 g_bolo[(size_t)Hc * 4096];
__device__ __nv_bfloat16 g_ohi[(size_t)Mtot * 4096];
__device__ __nv_bfloat16 g_olo[(size_t)Mtot * 4096];

// ------------------------------ helpers ------------------------------------
__device__ __forceinline__ uint32_t smem_u32(const void* p) {
    uint32_t a;
    asm("{ .reg .u64 t; cvta.to.shared.u64 t, %1; cvt.u32.u64 %0, t; }"
        : "=r"(a) : "l"(p));
    return a;
}
__device__ __forceinline__ void cp_async16(uint32_t saddr, const void* gaddr) {
    asm volatile("cp.async.cg.shared.global [%0], [%1], 16;"
                 :: "r"(saddr), "l"(gaddr) : "memory");
}
__device__ __forceinline__ void cp_async4(uint32_t saddr, const void* gaddr) {
    asm volatile("cp.async.ca.shared.global [%0], [%1], 4;"
                 :: "r"(saddr), "l"(gaddr) : "memory");
}
__device__ __forceinline__ void cp_commit() {
    asm volatile("cp.async.commit_group;" ::: "memory");
}
template <int N>
__device__ __forceinline__ void cp_wait() {
    asm volatile("cp.async.wait_group %0;" :: "n"(N) : "memory");
}
__device__ __forceinline__ void mma16816(float* c, const uint32_t* a, const uint32_t* b) {
    asm volatile(
        "mma.sync.aligned.m16n8k16.row.col.f32.bf16.bf16.f32 "
        "{%0,%1,%2,%3}, {%4,%5,%6,%7}, {%8,%9}, {%0,%1,%2,%3};"
        : "+f"(c[0]), "+f"(c[1]), "+f"(c[2]), "+f"(c[3])
        : "r"(a[0]), "r"(a[1]), "r"(a[2]), "r"(a[3]), "r"(b[0]), "r"(b[1]));
}
__device__ __forceinline__ void ldsm4(uint32_t* r, uint32_t addr) {
    asm volatile("ldmatrix.sync.aligned.m8n8.x4.shared.b16 {%0,%1,%2,%3}, [%4];"
                 : "=r"(r[0]), "=r"(r[1]), "=r"(r[2]), "=r"(r[3]) : "r"(addr));
}

// ---------------------------------------------------------------------------
// fused 3-plane split-bf16 GEMM: C = Ah*Bh^T + Ah*Bl^T + Al*Bh^T
// block tile 128(M) x 64(N), K chunk 64, 8 warps (4M x 2N), warp tile 32x32.
// RS=72 halves (144B row stride: 36 words -> 8 distinct ldmatrix bank groups).
// ---------------------------------------------------------------------------
#define RS      72
#define OFF_AL  9216           // 128*RS
#define OFF_BH  18432
#define OFF_BL  23040          // + 64*RS
#define STAGE_H 27648
#define GEMM_SMEM (2 * STAGE_H * 2)   // 110592 bytes

__global__ void __launch_bounds__(256, 2) mma_gemm_kernel(
    const __nv_bfloat16* __restrict__ Ah, const __nv_bfloat16* __restrict__ Al,
    const __nv_bfloat16* __restrict__ Bh, const __nv_bfloat16* __restrict__ Bl,
    float* __restrict__ C, int Kd, int N)
{
    extern __shared__ __align__(16) __nv_bfloat16 sm[];
    const int t = threadIdx.x, lane = t & 31, w = t >> 5;
    const int wm = (w & 3) * 32, wn = (w >> 2) * 32;
    const int grp = lane >> 2, q = lane & 3;
    const int bx = blockIdx.x, by = blockIdx.y;

    const int kiters = Kd >> 6;

    float acc[2][4][4];
#pragma unroll
    for (int mi = 0; mi < 2; mi++)
#pragma unroll
        for (int ni = 0; ni < 4; ni++)
#pragma unroll
            for (int j = 0; j < 4; j++) acc[mi][ni][j] = 0.f;

    uint32_t smb = smem_u32(sm);

    auto issue = [&](int stage, int kc) {
        size_t k0 = (size_t)kc << 6;
        uint32_t sb = smb + (uint32_t)(stage * STAGE_H) * 2;
        const __nv_bfloat16* Ab = Ah + (size_t)(by * 128) * Kd + k0;
        const __nv_bfloat16* Alb = Al + (size_t)(by * 128) * Kd + k0;
        const __nv_bfloat16* Bb = Bh + (size_t)(bx * 64) * Kd + k0;
        const __nv_bfloat16* Blb = Bl + (size_t)(bx * 64) * Kd + k0;
#pragma unroll
        for (int i = 0; i < 4; i++) {          // A planes: 1024 chunks each
            int idx = t + i * 256;
            int row = idx >> 3, seg = idx & 7;
            uint32_t so = (uint32_t)(row * RS + seg * 8) * 2;
            cp_async16(sb + so,              Ab  + (size_t)row * Kd + seg * 8);
            cp_async16(sb + OFF_AL * 2 + so, Alb + (size_t)row * Kd + seg * 8);
        }
#pragma unroll
        for (int i = 0; i < 2; i++) {          // B planes: 512 chunks each
            int idx = t + i * 256;
            int row = idx >> 3, seg = idx & 7;
            uint32_t so = (uint32_t)(row * RS + seg * 8) * 2;
            cp_async16(sb + OFF_BH * 2 + so, Bb  + (size_t)row * Kd + seg * 8);
            cp_async16(sb + OFF_BL * 2 + so, Blb + (size_t)row * Kd + seg * 8);
        }
        cp_commit();
    };

    issue(0, 0);

    const int r8  = lane & 7;
    const int hm  = (lane >> 3) & 1;
    const int hk2 = (lane >> 4) & 1;

    for (int it = 0; it < kiters; it++) {
        int buf = it & 1;
        if (it + 1 < kiters) { issue(buf ^ 1, it + 1); cp_wait<1>(); }
        else                 { cp_wait<0>(); }
        __syncthreads();

        uint32_t sb = smb + (uint32_t)(buf * STAGE_H) * 2;

#pragma unroll
        for (int ks = 0; ks < 4; ks++) {
            const int k16 = ks * 16;
            uint32_t ah[2][4], al[2][4];
            uint32_t aoff0 = (uint32_t)((wm + hm * 8 + r8) * RS + k16 + hk2 * 8) * 2;
            uint32_t aoff1 = aoff0 + 16 * RS * 2;
            ldsm4(ah[0], sb + aoff0);
            ldsm4(ah[1], sb + aoff1);
            ldsm4(al[0], sb + OFF_AL * 2 + aoff0);
            ldsm4(al[1], sb + OFF_AL * 2 + aoff1);
#pragma unroll
            for (int pi = 0; pi < 2; pi++) {
                uint32_t boff = (uint32_t)((wn + pi * 16 + hk2 * 8 + r8) * RS + k16 + hm * 8) * 2;
                uint32_t bh4[4], bl4[4];
                ldsm4(bh4, sb + OFF_BH * 2 + boff);
                ldsm4(bl4, sb + OFF_BL * 2 + boff);
#pragma unroll
                for (int sub = 0; sub < 2; sub++) {
                    int ni = pi * 2 + sub;
                    mma16816(acc[0][ni], ah[0], bh4 + sub * 2);
                    mma16816(acc[1][ni], ah[1], bh4 + sub * 2);
                    mma16816(acc[0][ni], ah[0], bl4 + sub * 2);
                    mma16816(acc[1][ni], ah[1], bl4 + sub * 2);
                    mma16816(acc[0][ni], al[0], bh4 + sub * 2);
                    mma16816(acc[1][ni], al[1], bh4 + sub * 2);
                }
            }
        }
        __syncthreads();
    }

#pragma unroll
    for (int mi = 0; mi < 2; mi++) {
        int row = by * 128 + wm + mi * 16 + grp;
#pragma unroll
        for (int ni = 0; ni < 4; ni++) {
            int col = bx * 64 + wn + ni * 8 + q * 2;
            float2 v0 = make_float2(acc[mi][ni][0], acc[mi][ni][1]);
            float2 v1 = make_float2(acc[mi][ni][2], acc[mi][ni][3]);
            *reinterpret_cast<float2*>(C + (size_t)row * N + col) = v0;
            *reinterpret_cast<float2*>(C + (size_t)(row + 8) * N + col) = v1;
        }
    }
}

// ---------------------------------------------------------------------------
__global__ void split_kernel(const float* __restrict__ src,
                             __nv_bfloat16* __restrict__ hi,
                             __nv_bfloat16* __restrict__ lo)
{
    size_t i = (size_t)blockIdx.x * 256 + threadIdx.x;
    float v = src[i];
    __nv_bfloat16 h = __float2bfloat16(v);
    hi[i] = h;
    lo[i] = __float2bfloat16(v - __bfloat162float(h));
}

__global__ void transpose_split_kernel(const float* __restrict__ W,
                                       __nv_bfloat16* __restrict__ Th,
                                       __nv_bfloat16* __restrict__ Tl,
                                       int K, int N)
{
    __shared__ float tile[32][33];
    int n0 = blockIdx.x * 32, k0 = blockIdx.y * 32;
    int tx = threadIdx.x, ty = threadIdx.y;
#pragma unroll
    for (int j = 0; j < 4; j++)
        tile[ty + j * 8][tx] = W[(size_t)(k0 + ty + j * 8) * N + n0 + tx];
    __syncthreads();
#pragma unroll
    for (int j = 0; j < 4; j++) {
        float v = tile[tx][ty + j * 8];
        __nv_bfloat16 h = __float2bfloat16(v);
        size_t o = (size_t)(n0 + ty + j * 8) * K + k0 + tx;
        Th[o] = h;
        Tl[o] = __float2bfloat16(v - __bfloat162float(h));
    }
}

// ---------------------------------------------------------------------------
// ba = x @ w_ba, split-K x8 into partial buffers (deterministic), then reduce.
// ---------------------------------------------------------------------------
__global__ void __launch_bounds__(256) ba_part_kernel(
    const float* __restrict__ x, const float* __restrict__ w_ba)
{
    int ks = blockIdx.x, by = blockIdx.y;
    __shared__ float As[8][128];
    __shared__ float Bs[8][64];
    int t = threadIdx.x, tx = t & 15, ty = t >> 4;
    float acc[8][4];
#pragma unroll
    for (int i = 0; i < 8; i++)
#pragma unroll
        for (int j = 0; j < 4; j++) acc[i][j] = 0.f;

    int arow = t >> 1, acol4 = (t & 1) * 4;
    int brow = t >> 5, bcol2 = (t & 31) * 2;
    const float* Aptr = x + (size_t)(by * 128 + arow) * Hc + ks * 256;

    for (int k0 = 0; k0 < 256; k0 += 8) {
        float4 a4 = *reinterpret_cast<const float4*>(Aptr + k0 + acol4);
        As[acol4 + 0][arow] = a4.x; As[acol4 + 1][arow] = a4.y;
        As[acol4 + 2][arow] = a4.z; As[acol4 + 3][arow] = a4.w;
        float2 b2 = *reinterpret_cast<const float2*>(
            w_ba + (size_t)(ks * 256 + k0 + brow) * 64 + bcol2);
        Bs[brow][bcol2] = b2.x; Bs[brow][bcol2 + 1] = b2.y;
        __syncthreads();
#pragma unroll
        for (int kk = 0; kk < 8; kk++) {
            float a[8], b[4];
#pragma unroll
            for (int i = 0; i < 8; i++) a[i] = As[kk][ty * 8 + i];
#pragma unroll
            for (int j = 0; j < 4; j++) b[j] = Bs[kk][tx * 4 + j];
#pragma unroll
            for (int i = 0; i < 8; i++)
#pragma unroll
                for (int j = 0; j < 4; j++)
                    acc[i][j] = fmaf(a[i], b[j], acc[i][j]);
        }
        __syncthreads();
    }
    float* dst = g_bapart + (size_t)ks * Mtot * 64;
#pragma unroll
    for (int i = 0; i < 8; i++) {
        int row = by * 128 + ty * 8 + i;
        float4 v = make_float4(acc[i][0], acc[i][1], acc[i][2], acc[i][3]);
        *reinterpret_cast<float4*>(dst + (size_t)row * 64 + tx * 4) = v;
    }
}

__global__ void ba_reduce_kernel()
{
    int i = blockIdx.x * 256 + threadIdx.x;
    float s = 0.f;
#pragma unroll
    for (int ks = 0; ks < 8; ks++) s += g_bapart[(size_t)ks * Mtot * 64 + i];
    g_ba[i] = s;
}

// ---------------------------------------------------------------------------
// causal conv K=4 + silu, fused with q/k l2norm (blocks are head-aligned).
// q -> g_qn (scaled DK^-0.5), k -> g_kn, v -> g_conv[.. 4096+..]
// ---------------------------------------------------------------------------
__global__ void conv_qknorm_kernel(const float* __restrict__ conv_w,
                                   const float* __restrict__ conv_b)
{
    int tid = threadIdx.x;
    int c = blockIdx.x * 256 + tid;
    int m = blockIdx.y;
    int s = m & (Sc - 1);
    int col;
    if (c < 2048)      col = (c >> 7) * 768 + (c & 127);
    else if (c < 4096) { int c2 = c - 2048; col = (c2 >> 7) * 768 + 128 + (c2 & 127); }
    else               { int c3 = c - 4096; col = (c3 >> 8) * 768 + 256 + (c3 & 255); }
    float acc = conv_b[c];
    const float* w = conv_w + c * 4;
#pragma unroll
    for (int j = 0; j < 4; j++) {
        int sp = s - 3 + j;
        if (sp >= 0)
            acc = fmaf(g_qkvz[(size_t)(m - 3 + j) * FQ + col], w[j], acc);
    }
    float val = acc / (1.f + expf(-acc));   // silu

    if (c < 4096) {
        float ss = val * val;
#pragma unroll
        for (int o = 16; o > 0; o >>= 1) ss += __shfl_xor_sync(0xffffffffu, ss, o);
        __shared__ float rb[8];
        if ((tid & 31) == 0) rb[tid >> 5] = ss;
        __syncthreads();
        int hw = (tid >> 7) * 4;
        float sum = rb[hw] + rb[hw + 1] + rb[hw + 2] + rb[hw + 3];
        if (c < 2048) {
            float rq = rsqrtf(sum + EPSc) * 0.08838834764831845f;
            g_qn[m * 2048 + c] = val * rq;
        } else {
            float rk = rsqrtf(sum + EPSc);
            g_kn[m * 2048 + (c - 2048)] = val * rk;
        }
    } else {
        g_conv[(size_t)m * CDc + c] = val;
    }
}

__global__ void gbeta_kernel(const float* __restrict__ a_log,
                             const float* __restrict__ dt_bias)
{
    int idx = blockIdx.x * 256 + threadIdx.x;
    int m = idx >> 5, hv = idx & 31;
    int hk = hv >> 1, gi = hv & 1;
    float bval = g_ba[m * 64 + hk * 4 + gi];
    float aval = g_ba[m * 64 + hk * 4 + 2 + gi];
    float x = aval + dt_bias[hv];
    float sp = (x > 20.f) ? x : log1pf(expf(x));
    g_gg[idx]   = -expf(a_log[hv]) * sp;
    g_beta[idx] = 1.f / (1.f + expf(-bval));
}

// ---------------------------------------------------------------------------
// gated delta scan, prefetched, 2 barriers/step. 128 blocks = (b,hv,vhalf).
// ---------------------------------------------------------------------------
__global__ void __launch_bounds__(256) scan_kernel()
{
    int bid = blockIdx.x;
    int bb = bid >> 6;
    int r = bid & 63;
    int hv = r >> 1, half = r & 1, hk = hv >> 1;
    int t = threadIdx.x;
    int vl = t & 63, qt = t >> 6, dbase = qt * 32;

    float S[32];
#pragma unroll
    for (int i = 0; i < 32; i++) S[i] = 0.f;

    __shared__ __align__(16) float kq[2][256];
    __shared__ __align__(16) float vsb[2][64];
    __shared__ float gbb[2][2];
    __shared__ float red[4][64], ored[4][64];

    const uint32_t skq = smem_u32(kq);
    const uint32_t svs = smem_u32(vsb);
    const uint32_t sgb = smem_u32(gbb);

    const float* kbase = g_kn + hk * 128;
    const float* qbase = g_qn + hk * 128;
    const float* vbase = g_conv + 4096 + hv * 128 + half * 64;
    const float* gbase = g_gg + hv;
    const float* bbase = g_beta + hv;

    auto prefetch = [&](int buf, int s) {
        int m = bb * Sc + s;
        if (t < 32)
            cp_async16(skq + buf * 1024 + t * 16, kbase + (size_t)m * 2048 + t * 4);
        else if (t < 64)
            cp_async16(skq + buf * 1024 + 512 + (t - 32) * 16,
                       qbase + (size_t)m * 2048 + (t - 32) * 4);
        else if (t < 80)
            cp_async16(svs + buf * 256 + (t - 64) * 16,
                       vbase + (size_t)m * CDc + (t - 64) * 4);
        else if (t == 80)
            cp_async4(sgb + buf * 8, gbase + m * 32);
        else if (t == 81)
            cp_async4(sgb + buf * 8 + 4, bbase + m * 32);
    };

    prefetch(0, 0);
    cp_commit();

    size_t obase = (size_t)bb * Sc * 4096 + hv * 128 + half * 64;

    for (int s = 0; s < Sc; s++) {
        int buf = s & 1;
        cp_wait<0>();
        __syncthreads();                       // bar1: buffer ready, ored(s-1) done
        if (s + 1 < Sc) { prefetch(buf ^ 1, s + 1); cp_commit(); }

        // overlapped output store for step s-1
        if (s > 0 && t < 64)
            g_opre[obase + (size_t)(s - 1) * 4096 + t] =
                ored[0][t] + ored[1][t] + ored[2][t] + ored[3][t];

        float eg   = expf(gbb[buf][0]);
        float beta = gbb[buf][1];
        const float* ks = kq[buf];
        const float* qs = kq[buf] + 128;
        const float* vs = vsb[buf];

        float p0 = 0.f, p1 = 0.f;
#pragma unroll
        for (int d = 0; d < 32; d += 2) {
            S[d]     *= eg;
            S[d + 1] *= eg;
            p0 = fmaf(ks[dbase + d],     S[d],     p0);
            p1 = fmaf(ks[dbase + d + 1], S[d + 1], p1);
        }
        red[qt][vl] = p0 + p1;
        __syncthreads();                       // bar2

        float delta = (vs[vl] - (red[0][vl] + red[1][vl] + red[2][vl] + red[3][vl])) * beta;
        float o0 = 0.f, o1 = 0.f;
#pragma unroll
        for (int d = 0; d < 32; d += 2) {
            S[d]     = fmaf(ks[dbase + d],     delta, S[d]);
            S[d + 1] = fmaf(ks[dbase + d + 1], delta, S[d + 1]);
            o0 = fmaf(qs[dbase + d],     S[d],     o0);
            o1 = fmaf(qs[dbase + d + 1], S[d + 1], o1);
        }
        ored[qt][vl] = o0 + o1;
    }
    __syncthreads();
    if (t < 64)
        g_opre[obase + (size_t)(Sc - 1) * 4096 + t] =
            ored[0][t] + ored[1][t] + ored[2][t] + ored[3][t];
}

// ---------------------------------------------------------------------------
__global__ void gate_norm_kernel(const float* __restrict__ norm_w)
{
    int m = blockIdx.x, hv = blockIdx.y, d = threadIdx.x;
    int hk = hv >> 1, gi = hv & 1;
    float z = g_qkvz[(size_t)m * FQ + hk * 768 + 512 + gi * 128 + d];
    float o = g_opre[(size_t)m * 4096 + hv * 128 + d] * (z / (1.f + expf(-z)));
    float ss = o * o;
#pragma unroll
    for (int off = 16; off > 0; off >>= 1) ss += __shfl_xor_sync(0xffffffffu, ss, off);
    __shared__ float rb[4];
    if ((d & 31) == 0) rb[d >> 5] = ss;
    __syncthreads();
    float sum = rb[0] + rb[1] + rb[2] + rb[3];
    float rs = rsqrtf(sum * (1.f / 128.f) + EPSc);
    float v = o * rs * norm_w[d];
    __nv_bfloat16 h = __float2bfloat16(v);
    size_t idx = (size_t)m * 4096 + hv * 128 + d;
    g_ohi[idx] = h;
    g_olo[idx] = __float2bfloat16(v - __bfloat162float(h));
}

// ---------------------------------------------------------------------------
extern "C" void kernel_launch(void* const* d_in, const int* in_sizes, int n_in,
                              void* d_out, int out_size)
{
    const float* x       = (const float*)d_in[0];
    const float* w_qkvz  = (const float*)d_in[1];
    const float* w_ba    = (const float*)d_in[2];
    const float* a_log   = (const float*)d_in[3];
    const float* dt_bias = (const float*)d_in[4];
    const float* conv_w  = (const float*)d_in[5];
    const float* conv_b  = (const float*)d_in[6];
    const float* norm_w  = (const float*)d_in[7];
    const float* w_o     = (const float*)d_in[8];
    float* out = (float*)d_out;

    float *p_qkvz;
    __nv_bfloat16 *p_xhi, *p_xlo, *p_bqhi, *p_bqlo, *p_bohi, *p_bolo, *p_ohi, *p_olo;
    cudaGetSymbolAddress((void**)&p_qkvz, g_qkvz);
    cudaGetSymbolAddress((void**)&p_xhi,  g_xhi);
    cudaGetSymbolAddress((void**)&p_xlo,  g_xlo);
    cudaGetSymbolAddress((void**)&p_bqhi, g_bqhi);
    cudaGetSymbolAddress((void**)&p_bqlo, g_bqlo);
    cudaGetSymbolAddress((void**)&p_bohi, g_bohi);
    cudaGetSymbolAddress((void**)&p_bolo, g_bolo);
    cudaGetSymbolAddress((void**)&p_ohi,  g_ohi);
    cudaGetSymbolAddress((void**)&p_olo,  g_olo);

    cudaFuncSetAttribute(mma_gemm_kernel,
                         cudaFuncAttributeMaxDynamicSharedMemorySize, GEMM_SMEM);

    split_kernel<<<(Mtot * Hc) / 256, 256>>>(x, p_xhi, p_xlo);
    transpose_split_kernel<<<dim3(FQ / 32, Hc / 32), dim3(32, 8)>>>(w_qkvz, p_bqhi, p_bqlo, Hc, FQ);
    transpose_split_kernel<<<dim3(Hc / 32, 4096 / 32), dim3(32, 8)>>>(w_o, p_bohi, p_bolo, 4096, Hc);

    // K1: qkvz = x @ w_qkvz
    mma_gemm_kernel<<<dim3(FQ / 64, Mtot / 128), 256, GEMM_SMEM>>>(
        p_xhi, p_xlo, p_bqhi, p_bqlo, p_qkvz, Hc, FQ);
    // K2: ba = x @ w_ba (split-K x8 + reduce)
    ba_part_kernel<<<dim3(8, Mtot / 128), 256>>>(x, w_ba);
    ba_reduce_kernel<<<(Mtot * 64) / 256, 256>>>();
    // K3+K4: conv + silu + q/k l2norm (fused)
    conv_qknorm_kernel<<<dim3(CDc / 256, Mtot), 256>>>(conv_w, conv_b);
    // K5: gates
    gbeta_kernel<<<(Mtot * HVc) / 256, 256>>>(a_log, dt_bias);
    // K6: recurrent scan
    scan_kernel<<<128, 256>>>();
    // K7: gate + rmsnorm + bf16 split
    gate_norm_kernel<<<dim3(Mtot, HVc), 128>>>(norm_w);
    // K8: out = o @ w_o
    mma_gemm_kernel<<<dim3(Hc / 64, Mtot / 128), 256, GEMM_SMEM>>>(
        p_ohi, p_olo, p_bohi, p_bolo, out, 4096, Hc);
}

// round 7
// speedup vs baseline: 2.6024x; 1.0643x over previous
#include <cuda_runtime.h>
#include <cuda_bf16.h>
#include <math.h>
#include <stdint.h>

// ---------------------------------------------------------------------------
// GatedDeltaNet  B=2 S=2048 H=2048 HK=16 HV=32 DK=DV=128 G=2 K=4
// Round 7:
//  - GEMM back to 128x128 tile / k32 (best measured shape), with
//    (a) ONE __syncthreads per k-iter (wait -> sync -> issue -> compute)
//    (b) MMA order with same-accumulator spacing 4 (RAW stall removal)
//  - keeps: ba split-K x8, fused conv+silu+qknorm, 2-barrier prefetched scan
// ---------------------------------------------------------------------------

#define Sc    2048
#define Hc    2048
#define HKc   16
#define HVc   32
#define CDc   8192
#define FQ    12288
#define Mtot  4096
#define EPSc  1e-6f

// ------------------------------ scratch ------------------------------------
__device__ float g_qkvz[(size_t)Mtot * FQ];
__device__ float g_ba[Mtot * 64];
__device__ float g_bapart[8 * Mtot * 64];
__device__ float g_conv[(size_t)Mtot * CDc];
__device__ float g_qn[Mtot * 2048];
__device__ float g_kn[Mtot * 2048];
__device__ float g_gg[Mtot * HVc];
__device__ float g_beta[Mtot * HVc];
__device__ float g_opre[(size_t)Mtot * 4096];

__device__ __nv_bfloat16 g_xhi[(size_t)Mtot * Hc];
__device__ __nv_bfloat16 g_xlo[(size_t)Mtot * Hc];
__device__ __nv_bfloat16 g_bqhi[(size_t)FQ * Hc];
__device__ __nv_bfloat16 g_bqlo[(size_t)FQ * Hc];
__device__ __nv_bfloat16 g_bohi[(size_t)Hc * 4096];
__device__ __nv_bfloat16 g_bolo[(size_t)Hc * 4096];
__device__ __nv_bfloat16 g_ohi[(size_t)Mtot * 4096];
__device__ __nv_bfloat16 g_olo[(size_t)Mtot * 4096];

// ------------------------------ helpers ------------------------------------
__device__ __forceinline__ uint32_t smem_u32(const void* p) {
    uint32_t a;
    asm("{ .reg .u64 t; cvta.to.shared.u64 t, %1; cvt.u32.u64 %0, t; }"
        : "=r"(a) : "l"(p));
    return a;
}
__device__ __forceinline__ void cp_async16(uint32_t saddr, const void* gaddr) {
    asm volatile("cp.async.cg.shared.global [%0], [%1], 16;"
                 :: "r"(saddr), "l"(gaddr) : "memory");
}
__device__ __forceinline__ void cp_async4(uint32_t saddr, const void* gaddr) {
    asm volatile("cp.async.ca.shared.global [%0], [%1], 4;"
                 :: "r"(saddr), "l"(gaddr) : "memory");
}
__device__ __forceinline__ void cp_commit() {
    asm volatile("cp.async.commit_group;" ::: "memory");
}
template <int N>
__device__ __forceinline__ void cp_wait() {
    asm volatile("cp.async.wait_group %0;" :: "n"(N) : "memory");
}
__device__ __forceinline__ void mma16816(float* c, const uint32_t* a, const uint32_t* b) {
    asm volatile(
        "mma.sync.aligned.m16n8k16.row.col.f32.bf16.bf16.f32 "
        "{%0,%1,%2,%3}, {%4,%5,%6,%7}, {%8,%9}, {%0,%1,%2,%3};"
        : "+f"(c[0]), "+f"(c[1]), "+f"(c[2]), "+f"(c[3])
        : "r"(a[0]), "r"(a[1]), "r"(a[2]), "r"(a[3]), "r"(b[0]), "r"(b[1]));
}
__device__ __forceinline__ void ldsm4(uint32_t* r, uint32_t addr) {
    asm volatile("ldmatrix.sync.aligned.m8n8.x4.shared.b16 {%0,%1,%2,%3}, [%4];"
                 : "=r"(r[0]), "=r"(r[1]), "=r"(r[2]), "=r"(r[3]) : "r"(addr));
}

// ---------------------------------------------------------------------------
// fused 3-plane split-bf16 GEMM: C = Ah*Bh^T + Ah*Bl^T + Al*Bh^T
// block tile 128x128, 8 warps (4M x 2N), warp tile 32x64, K chunk 32,
// cp.async double-buffered, ldmatrix, ONE sync per iter, acc-spacing-4 MMAs.
// ---------------------------------------------------------------------------
#define RS 40                 // smem row stride in halves (80B, conflict-free)
#define TILE_H (128 * RS)     // halves per 128x32 tile
#define GEMM_SMEM (2 * 4 * TILE_H * 2)   // 81920 bytes

__global__ void __launch_bounds__(256, 2) mma_gemm_kernel(
    const __nv_bfloat16* __restrict__ Ah, const __nv_bfloat16* __restrict__ Al,
    const __nv_bfloat16* __restrict__ Bh, const __nv_bfloat16* __restrict__ Bl,
    float* __restrict__ C, int Kd, int N)
{
    extern __shared__ __align__(16) __nv_bfloat16 sm[];
    const int t = threadIdx.x, lane = t & 31, w = t >> 5;
    const int wm = (w & 3) * 32, wn = (w >> 2) * 64;
    const int grp = lane >> 2, q = lane & 3;
    const int bx = blockIdx.x, by = blockIdx.y;

    const int kiters = Kd >> 5;

    float acc[2][8][4];
#pragma unroll
    for (int mi = 0; mi < 2; mi++)
#pragma unroll
        for (int ni = 0; ni < 8; ni++)
#pragma unroll
            for (int j = 0; j < 4; j++) acc[mi][ni][j] = 0.f;

    const int c0 = t, c1 = t + 256;
    const int r0 = c0 >> 2, s0 = c0 & 3;
    const int r1 = c1 >> 2, s1 = c1 & 3;

    uint32_t smb = smem_u32(sm);

    auto issue = [&](int stage, int kc) {
        size_t k0 = (size_t)kc << 5;
        const __nv_bfloat16* srcs[4] = {
            Ah + (size_t)(by * 128) * Kd, Al + (size_t)(by * 128) * Kd,
            Bh + (size_t)(bx * 128) * Kd, Bl + (size_t)(bx * 128) * Kd };
#pragma unroll
        for (int ti = 0; ti < 4; ti++) {
            uint32_t base = smb + (uint32_t)((stage * 4 + ti) * TILE_H) * 2;
            cp_async16(base + (r0 * RS + s0 * 8) * 2,
                       srcs[ti] + (size_t)r0 * Kd + k0 + s0 * 8);
            cp_async16(base + (r1 * RS + s1 * 8) * 2,
                       srcs[ti] + (size_t)r1 * Kd + k0 + s1 * 8);
        }
        cp_commit();
    };

    issue(0, 0);

    const int r8  = lane & 7;
    const int hm  = (lane >> 3) & 1;
    const int hk2 = (lane >> 4) & 1;

    for (int it = 0; it < kiters; it++) {
        int buf = it & 1;
        cp_wait<0>();
        __syncthreads();          // everyone done reading buf^1; buf is loaded
        if (it + 1 < kiters) issue(buf ^ 1, it + 1);   // overlaps with compute

        uint32_t sahb = smb + (uint32_t)((buf * 4 + 0) * TILE_H) * 2;
        uint32_t salb = smb + (uint32_t)((buf * 4 + 1) * TILE_H) * 2;
        uint32_t sbhb = smb + (uint32_t)((buf * 4 + 2) * TILE_H) * 2;
        uint32_t sblb = smb + (uint32_t)((buf * 4 + 3) * TILE_H) * 2;

#pragma unroll
        for (int ks = 0; ks < 2; ks++) {
            const int k16 = ks * 16;
            uint32_t ah[2][4], al[2][4];
            uint32_t aoff0 = (uint32_t)((wm + hm * 8 + r8) * RS + k16 + hk2 * 8) * 2;
            uint32_t aoff1 = aoff0 + 16 * RS * 2;
            ldsm4(ah[0], sahb + aoff0);
            ldsm4(ah[1], sahb + aoff1);
            ldsm4(al[0], salb + aoff0);
            ldsm4(al[1], salb + aoff1);
#pragma unroll
            for (int pi = 0; pi < 4; pi++) {
                uint32_t boff = (uint32_t)((wn + pi * 16 + hk2 * 8 + r8) * RS + k16 + hm * 8) * 2;
                uint32_t bh4[4], bl4[4];
                ldsm4(bh4, sbhb + boff);
                ldsm4(bl4, sblb + boff);
                int n0 = pi * 2, n1 = pi * 2 + 1;
                // same-accumulator spacing 4:
                mma16816(acc[0][n0], ah[0], bh4 + 0);
                mma16816(acc[1][n0], ah[1], bh4 + 0);
                mma16816(acc[0][n1], ah[0], bh4 + 2);
                mma16816(acc[1][n1], ah[1], bh4 + 2);
                mma16816(acc[0][n0], ah[0], bl4 + 0);
                mma16816(acc[1][n0], ah[1], bl4 + 0);
                mma16816(acc[0][n1], ah[0], bl4 + 2);
                mma16816(acc[1][n1], ah[1], bl4 + 2);
                mma16816(acc[0][n0], al[0], bh4 + 0);
                mma16816(acc[1][n0], al[1], bh4 + 0);
                mma16816(acc[0][n1], al[0], bh4 + 2);
                mma16816(acc[1][n1], al[1], bh4 + 2);
            }
        }
    }

    __syncthreads();
#pragma unroll
    for (int mi = 0; mi < 2; mi++) {
        int row = by * 128 + wm + mi * 16 + grp;
#pragma unroll
        for (int ni = 0; ni < 8; ni++) {
            int col = bx * 128 + wn + ni * 8 + q * 2;
            float2 v0 = make_float2(acc[mi][ni][0], acc[mi][ni][1]);
            float2 v1 = make_float2(acc[mi][ni][2], acc[mi][ni][3]);
            *reinterpret_cast<float2*>(C + (size_t)row * N + col) = v0;
            *reinterpret_cast<float2*>(C + (size_t)(row + 8) * N + col) = v1;
        }
    }
}

// ---------------------------------------------------------------------------
__global__ void split_kernel(const float* __restrict__ src,
                             __nv_bfloat16* __restrict__ hi,
                             __nv_bfloat16* __restrict__ lo)
{
    size_t i = (size_t)blockIdx.x * 256 + threadIdx.x;
    float v = src[i];
    __nv_bfloat16 h = __float2bfloat16(v);
    hi[i] = h;
    lo[i] = __float2bfloat16(v - __bfloat162float(h));
}

__global__ void transpose_split_kernel(const float* __restrict__ W,
                                       __nv_bfloat16* __restrict__ Th,
                                       __nv_bfloat16* __restrict__ Tl,
                                       int K, int N)
{
    __shared__ float tile[32][33];
    int n0 = blockIdx.x * 32, k0 = blockIdx.y * 32;
    int tx = threadIdx.x, ty = threadIdx.y;
#pragma unroll
    for (int j = 0; j < 4; j++)
        tile[ty + j * 8][tx] = W[(size_t)(k0 + ty + j * 8) * N + n0 + tx];
    __syncthreads();
#pragma unroll
    for (int j = 0; j < 4; j++) {
        float v = tile[tx][ty + j * 8];
        __nv_bfloat16 h = __float2bfloat16(v);
        size_t o = (size_t)(n0 + ty + j * 8) * K + k0 + tx;
        Th[o] = h;
        Tl[o] = __float2bfloat16(v - __bfloat162float(h));
    }
}

// ---------------------------------------------------------------------------
// ba = x @ w_ba, split-K x8 (deterministic) + reduce.
// ---------------------------------------------------------------------------
__global__ void __launch_bounds__(256) ba_part_kernel(
    const float* __restrict__ x, const float* __restrict__ w_ba)
{
    int ks = blockIdx.x, by = blockIdx.y;
    __shared__ float As[8][128];
    __shared__ float Bs[8][64];
    int t = threadIdx.x, tx = t & 15, ty = t >> 4;
    float acc[8][4];
#pragma unroll
    for (int i = 0; i < 8; i++)
#pragma unroll
        for (int j = 0; j < 4; j++) acc[i][j] = 0.f;

    int arow = t >> 1, acol4 = (t & 1) * 4;
    int brow = t >> 5, bcol2 = (t & 31) * 2;
    const float* Aptr = x + (size_t)(by * 128 + arow) * Hc + ks * 256;

    for (int k0 = 0; k0 < 256; k0 += 8) {
        float4 a4 = *reinterpret_cast<const float4*>(Aptr + k0 + acol4);
        As[acol4 + 0][arow] = a4.x; As[acol4 + 1][arow] = a4.y;
        As[acol4 + 2][arow] = a4.z; As[acol4 + 3][arow] = a4.w;
        float2 b2 = *reinterpret_cast<const float2*>(
            w_ba + (size_t)(ks * 256 + k0 + brow) * 64 + bcol2);
        Bs[brow][bcol2] = b2.x; Bs[brow][bcol2 + 1] = b2.y;
        __syncthreads();
#pragma unroll
        for (int kk = 0; kk < 8; kk++) {
            float a[8], b[4];
#pragma unroll
            for (int i = 0; i < 8; i++) a[i] = As[kk][ty * 8 + i];
#pragma unroll
            for (int j = 0; j < 4; j++) b[j] = Bs[kk][tx * 4 + j];
#pragma unroll
            for (int i = 0; i < 8; i++)
#pragma unroll
                for (int j = 0; j < 4; j++)
                    acc[i][j] = fmaf(a[i], b[j], acc[i][j]);
        }
        __syncthreads();
    }
    float* dst = g_bapart + (size_t)ks * Mtot * 64;
#pragma unroll
    for (int i = 0; i < 8; i++) {
        int row = by * 128 + ty * 8 + i;
        float4 v = make_float4(acc[i][0], acc[i][1], acc[i][2], acc[i][3]);
        *reinterpret_cast<float4*>(dst + (size_t)row * 64 + tx * 4) = v;
    }
}

__global__ void ba_reduce_kernel()
{
    int i = blockIdx.x * 256 + threadIdx.x;
    float s = 0.f;
#pragma unroll
    for (int ks = 0; ks < 8; ks++) s += g_bapart[(size_t)ks * Mtot * 64 + i];
    g_ba[i] = s;
}

// ---------------------------------------------------------------------------
// causal conv K=4 + silu, fused with q/k l2norm.
// ---------------------------------------------------------------------------
__global__ void conv_qknorm_kernel(const float* __restrict__ conv_w,
                                   const float* __restrict__ conv_b)
{
    int tid = threadIdx.x;
    int c = blockIdx.x * 256 + tid;
    int m = blockIdx.y;
    int s = m & (Sc - 1);
    int col;
    if (c < 2048)      col = (c >> 7) * 768 + (c & 127);
    else if (c < 4096) { int c2 = c - 2048; col = (c2 >> 7) * 768 + 128 + (c2 & 127); }
    else               { int c3 = c - 4096; col = (c3 >> 8) * 768 + 256 + (c3 & 255); }
    float acc = conv_b[c];
    const float* w = conv_w + c * 4;
#pragma unroll
    for (int j = 0; j < 4; j++) {
        int sp = s - 3 + j;
        if (sp >= 0)
            acc = fmaf(g_qkvz[(size_t)(m - 3 + j) * FQ + col], w[j], acc);
    }
    float val = acc / (1.f + expf(-acc));   // silu

    if (c < 4096) {
        float ss = val * val;
#pragma unroll
        for (int o = 16; o > 0; o >>= 1) ss += __shfl_xor_sync(0xffffffffu, ss, o);
        __shared__ float rb[8];
        if ((tid & 31) == 0) rb[tid >> 5] = ss;
        __syncthreads();
        int hw = (tid >> 7) * 4;
        float sum = rb[hw] + rb[hw + 1] + rb[hw + 2] + rb[hw + 3];
        if (c < 2048) {
            float rq = rsqrtf(sum + EPSc) * 0.08838834764831845f;
            g_qn[m * 2048 + c] = val * rq;
        } else {
            float rk = rsqrtf(sum + EPSc);
            g_kn[m * 2048 + (c - 2048)] = val * rk;
        }
    } else {
        g_conv[(size_t)m * CDc + c] = val;
    }
}

__global__ void gbeta_kernel(const float* __restrict__ a_log,
                             const float* __restrict__ dt_bias)
{
    int idx = blockIdx.x * 256 + threadIdx.x;
    int m = idx >> 5, hv = idx & 31;
    int hk = hv >> 1, gi = hv & 1;
    float bval = g_ba[m * 64 + hk * 4 + gi];
    float aval = g_ba[m * 64 + hk * 4 + 2 + gi];
    float x = aval + dt_bias[hv];
    float sp = (x > 20.f) ? x : log1pf(expf(x));
    g_gg[idx]   = -expf(a_log[hv]) * sp;
    g_beta[idx] = 1.f / (1.f + expf(-bval));
}

// ---------------------------------------------------------------------------
// gated delta scan, prefetched, 2 barriers/step. 128 blocks = (b,hv,vhalf).
// ---------------------------------------------------------------------------
__global__ void __launch_bounds__(256) scan_kernel()
{
    int bid = blockIdx.x;
    int bb = bid >> 6;
    int r = bid & 63;
    int hv = r >> 1, half = r & 1, hk = hv >> 1;
    int t = threadIdx.x;
    int vl = t & 63, qt = t >> 6, dbase = qt * 32;

    float S[32];
#pragma unroll
    for (int i = 0; i < 32; i++) S[i] = 0.f;

    __shared__ __align__(16) float kq[2][256];
    __shared__ __align__(16) float vsb[2][64];
    __shared__ float gbb[2][2];
    __shared__ float red[4][64], ored[4][64];

    const uint32_t skq = smem_u32(kq);
    const uint32_t svs = smem_u32(vsb);
    const uint32_t sgb = smem_u32(gbb);

    const float* kbase = g_kn + hk * 128;
    const float* qbase = g_qn + hk * 128;
    const float* vbase = g_conv + 4096 + hv * 128 + half * 64;
    const float* gbase = g_gg + hv;
    const float* bbase = g_beta + hv;

    auto prefetch = [&](int buf, int s) {
        int m = bb * Sc + s;
        if (t < 32)
            cp_async16(skq + buf * 1024 + t * 16, kbase + (size_t)m * 2048 + t * 4);
        else if (t < 64)
            cp_async16(skq + buf * 1024 + 512 + (t - 32) * 16,
                       qbase + (size_t)m * 2048 + (t - 32) * 4);
        else if (t < 80)
            cp_async16(svs + buf * 256 + (t - 64) * 16,
                       vbase + (size_t)m * CDc + (t - 64) * 4);
        else if (t == 80)
            cp_async4(sgb + buf * 8, gbase + m * 32);
        else if (t == 81)
            cp_async4(sgb + buf * 8 + 4, bbase + m * 32);
    };

    prefetch(0, 0);
    cp_commit();

    size_t obase = (size_t)bb * Sc * 4096 + hv * 128 + half * 64;

    for (int s = 0; s < Sc; s++) {
        int buf = s & 1;
        cp_wait<0>();
        __syncthreads();                       // bar1
        if (s + 1 < Sc) { prefetch(buf ^ 1, s + 1); cp_commit(); }

        if (s > 0 && t < 64)
            g_opre[obase + (size_t)(s - 1) * 4096 + t] =
                ored[0][t] + ored[1][t] + ored[2][t] + ored[3][t];

        float eg   = expf(gbb[buf][0]);
        float beta = gbb[buf][1];
        const float* ks = kq[buf];
        const float* qs = kq[buf] + 128;
        const float* vs = vsb[buf];

        float p0 = 0.f, p1 = 0.f;
#pragma unroll
        for (int d = 0; d < 32; d += 2) {
            S[d]     *= eg;
            S[d + 1] *= eg;
            p0 = fmaf(ks[dbase + d],     S[d],     p0);
            p1 = fmaf(ks[dbase + d + 1], S[d + 1], p1);
        }
        red[qt][vl] = p0 + p1;
        __syncthreads();                       // bar2

        float delta = (vs[vl] - (red[0][vl] + red[1][vl] + red[2][vl] + red[3][vl])) * beta;
        float o0 = 0.f, o1 = 0.f;
#pragma unroll
        for (int d = 0; d < 32; d += 2) {
            S[d]     = fmaf(ks[dbase + d],     delta, S[d]);
            S[d + 1] = fmaf(ks[dbase + d + 1], delta, S[d + 1]);
            o0 = fmaf(qs[dbase + d],     S[d],     o0);
            o1 = fmaf(qs[dbase + d + 1], S[d + 1], o1);
        }
        ored[qt][vl] = o0 + o1;
    }
    __syncthreads();
    if (t < 64)
        g_opre[obase + (size_t)(Sc - 1) * 4096 + t] =
            ored[0][t] + ored[1][t] + ored[2][t] + ored[3][t];
}

// ---------------------------------------------------------------------------
__global__ void gate_norm_kernel(const float* __restrict__ norm_w)
{
    int m = blockIdx.x, hv = blockIdx.y, d = threadIdx.x;
    int hk = hv >> 1, gi = hv & 1;
    float z = g_qkvz[(size_t)m * FQ + hk * 768 + 512 + gi * 128 + d];
    float o = g_opre[(size_t)m * 4096 + hv * 128 + d] * (z / (1.f + expf(-z)));
    float ss = o * o;
#pragma unroll
    for (int off = 16; off > 0; off >>= 1) ss += __shfl_xor_sync(0xffffffffu, ss, off);
    __shared__ float rb[4];
    if ((d & 31) == 0) rb[d >> 5] = ss;
    __syncthreads();
    float sum = rb[0] + rb[1] + rb[2] + rb[3];
    float rs = rsqrtf(sum * (1.f / 128.f) + EPSc);
    float v = o * rs * norm_w[d];
    __nv_bfloat16 h = __float2bfloat16(v);
    size_t idx = (size_t)m * 4096 + hv * 128 + d;
    g_ohi[idx] = h;
    g_olo[idx] = __float2bfloat16(v - __bfloat162float(h));
}

// ---------------------------------------------------------------------------
extern "C" void kernel_launch(void* const* d_in, const int* in_sizes, int n_in,
                              void* d_out, int out_size)
{
    const float* x       = (const float*)d_in[0];
    const float* w_qkvz  = (const float*)d_in[1];
    const float* w_ba    = (const float*)d_in[2];
    const float* a_log   = (const float*)d_in[3];
    const float* dt_bias = (const float*)d_in[4];
    const float* conv_w  = (const float*)d_in[5];
    const float* conv_b  = (const float*)d_in[6];
    const float* norm_w  = (const float*)d_in[7];
    const float* w_o     = (const float*)d_in[8];
    float* out = (float*)d_out;

    float *p_qkvz;
    __nv_bfloat16 *p_xhi, *p_xlo, *p_bqhi, *p_bqlo, *p_bohi, *p_bolo, *p_ohi, *p_olo;
    cudaGetSymbolAddress((void**)&p_qkvz, g_qkvz);
    cudaGetSymbolAddress((void**)&p_xhi,  g_xhi);
    cudaGetSymbolAddress((void**)&p_xlo,  g_xlo);
    cudaGetSymbolAddress((void**)&p_bqhi, g_bqhi);
    cudaGetSymbolAddress((void**)&p_bqlo, g_bqlo);
    cudaGetSymbolAddress((void**)&p_bohi, g_bohi);
    cudaGetSymbolAddress((void**)&p_bolo, g_bolo);
    cudaGetSymbolAddress((void**)&p_ohi,  g_ohi);
    cudaGetSymbolAddress((void**)&p_olo,  g_olo);

    cudaFuncSetAttribute(mma_gemm_kernel,
                         cudaFuncAttributeMaxDynamicSharedMemorySize, GEMM_SMEM);

    split_kernel<<<(Mtot * Hc) / 256, 256>>>(x, p_xhi, p_xlo);
    transpose_split_kernel<<<dim3(FQ / 32, Hc / 32), dim3(32, 8)>>>(w_qkvz, p_bqhi, p_bqlo, Hc, FQ);
    transpose_split_kernel<<<dim3(Hc / 32, 4096 / 32), dim3(32, 8)>>>(w_o, p_bohi, p_bolo, 4096, Hc);

    // K1: qkvz = x @ w_qkvz
    mma_gemm_kernel<<<dim3(FQ / 128, Mtot / 128), 256, GEMM_SMEM>>>(
        p_xhi, p_xlo, p_bqhi, p_bqlo, p_qkvz, Hc, FQ);
    // K2: ba = x @ w_ba (split-K x8 + reduce)
    ba_part_kernel<<<dim3(8, Mtot / 128), 256>>>(x, w_ba);
    ba_reduce_kernel<<<(Mtot * 64) / 256, 256>>>();
    // K3+K4: conv + silu + q/k l2norm (fused)
    conv_qknorm_kernel<<<dim3(CDc / 256, Mtot), 256>>>(conv_w, conv_b);
    // K5: gates
    gbeta_kernel<<<(Mtot * HVc) / 256, 256>>>(a_log, dt_bias);
    // K6: recurrent scan
    scan_kernel<<<128, 256>>>();
    // K7: gate + rmsnorm + bf16 split
    gate_norm_kernel<<<dim3(Mtot, HVc), 128>>>(norm_w);
    // K8: out = o @ w_o
    mma_gemm_kernel<<<dim3(Hc / 128, Mtot / 128), 256, GEMM_SMEM>>>(
        p_ohi, p_olo, p_bohi, p_bolo, out, 4096, Hc);
}

// round 8
// speedup vs baseline: 2.7562x; 1.0591x over previous
#include <cuda_runtime.h>
#include <cuda_bf16.h>
#include <math.h>
#include <stdint.h>

// ---------------------------------------------------------------------------
// GatedDeltaNet  B=2 S=2048 H=2048 HK=16 HV=32 DK=DV=128 G=2 K=4
// Round 8:
//  - GEMM: panel-swizzled rasterization (GX=8 bx-tiles x all by) so the
//    B-panel stays L2-resident; B streamed from DRAM ~once instead of 32x
//  - scan: prefetch depth 2 (3 buffers, wait_group<1>), ILP-4 reductions
//  - keeps: 128x128/k32 tile, 1-sync loop, spacing-4 MMAs, split-K ba,
//    fused conv+qknorm, 2-barrier scan core
// ---------------------------------------------------------------------------

#define Sc    2048
#define Hc    2048
#define HKc   16
#define HVc   32
#define CDc   8192
#define FQ    12288
#define Mtot  4096
#define EPSc  1e-6f

// ------------------------------ scratch ------------------------------------
__device__ float g_qkvz[(size_t)Mtot * FQ];
__device__ float g_ba[Mtot * 64];
__device__ float g_bapart[8 * Mtot * 64];
__device__ float g_conv[(size_t)Mtot * CDc];
__device__ float g_qn[Mtot * 2048];
__device__ float g_kn[Mtot * 2048];
__device__ float g_gg[Mtot * HVc];
__device__ float g_beta[Mtot * HVc];
__device__ float g_opre[(size_t)Mtot * 4096];

__device__ __nv_bfloat16 g_xhi[(size_t)Mtot * Hc];
__device__ __nv_bfloat16 g_xlo[(size_t)Mtot * Hc];
__device__ __nv_bfloat16 g_bqhi[(size_t)FQ * Hc];
__device__ __nv_bfloat16 g_bqlo[(size_t)FQ * Hc];
__device__ __nv_bfloat16 g_bohi[(size_t)Hc * 4096];
__device__ __nv_bfloat16 g_bolo[(size_t)Hc * 4096];
__device__ __nv_bfloat16 g_ohi[(size_t)Mtot * 4096];
__device__ __nv_bfloat16 g_olo[(size_t)Mtot * 4096];

// ------------------------------ helpers ------------------------------------
__device__ __forceinline__ uint32_t smem_u32(const void* p) {
    uint32_t a;
    asm("{ .reg .u64 t; cvta.to.shared.u64 t, %1; cvt.u32.u64 %0, t; }"
        : "=r"(a) : "l"(p));
    return a;
}
__device__ __forceinline__ void cp_async16(uint32_t saddr, const void* gaddr) {
    asm volatile("cp.async.cg.shared.global [%0], [%1], 16;"
                 :: "r"(saddr), "l"(gaddr) : "memory");
}
__device__ __forceinline__ void cp_async4(uint32_t saddr, const void* gaddr) {
    asm volatile("cp.async.ca.shared.global [%0], [%1], 4;"
                 :: "r"(saddr), "l"(gaddr) : "memory");
}
__device__ __forceinline__ void cp_commit() {
    asm volatile("cp.async.commit_group;" ::: "memory");
}
template <int N>
__device__ __forceinline__ void cp_wait() {
    asm volatile("cp.async.wait_group %0;" :: "n"(N) : "memory");
}
__device__ __forceinline__ void mma16816(float* c, const uint32_t* a, const uint32_t* b) {
    asm volatile(
        "mma.sync.aligned.m16n8k16.row.col.f32.bf16.bf16.f32 "
        "{%0,%1,%2,%3}, {%4,%5,%6,%7}, {%8,%9}, {%0,%1,%2,%3};"
        : "+f"(c[0]), "+f"(c[1]), "+f"(c[2]), "+f"(c[3])
        : "r"(a[0]), "r"(a[1]), "r"(a[2]), "r"(a[3]), "r"(b[0]), "r"(b[1]));
}
__device__ __forceinline__ void ldsm4(uint32_t* r, uint32_t addr) {
    asm volatile("ldmatrix.sync.aligned.m8n8.x4.shared.b16 {%0,%1,%2,%3}, [%4];"
                 : "=r"(r[0]), "=r"(r[1]), "=r"(r[2]), "=r"(r[3]) : "r"(addr));
}

// ---------------------------------------------------------------------------
// fused 3-plane split-bf16 GEMM, panel-swizzled 1D grid.
// block tile 128x128, 8 warps (4M x 2N), warp tile 32x64, K chunk 32.
// ---------------------------------------------------------------------------
#define RS 40
#define TILE_H (128 * RS)
#define GEMM_SMEM (2 * 4 * TILE_H * 2)   // 81920 bytes
#define GXP 8                            // bx tiles per L2 panel

__global__ void __launch_bounds__(256, 2) mma_gemm_kernel(
    const __nv_bfloat16* __restrict__ Ah, const __nv_bfloat16* __restrict__ Al,
    const __nv_bfloat16* __restrict__ Bh, const __nv_bfloat16* __restrict__ Bl,
    float* __restrict__ C, int Kd, int N)
{
    extern __shared__ __align__(16) __nv_bfloat16 sm[];
    const int t = threadIdx.x, lane = t & 31, w = t >> 5;
    const int wm = (w & 3) * 32, wn = (w >> 2) * 64;
    const int grp = lane >> 2, q = lane & 3;

    // panel swizzle: walk 8 bx-tiles x all 32 by-tiles per panel
    const int panel_sz = GXP * (Mtot / 128);
    const int panel = blockIdx.x / panel_sz;
    const int rem   = blockIdx.x % panel_sz;
    const int bx = panel * GXP + (rem % GXP);
    const int by = rem / GXP;

    const int kiters = Kd >> 5;

    float acc[2][8][4];
#pragma unroll
    for (int mi = 0; mi < 2; mi++)
#pragma unroll
        for (int ni = 0; ni < 8; ni++)
#pragma unroll
            for (int j = 0; j < 4; j++) acc[mi][ni][j] = 0.f;

    const int c0 = t, c1 = t + 256;
    const int r0 = c0 >> 2, s0 = c0 & 3;
    const int r1 = c1 >> 2, s1 = c1 & 3;

    uint32_t smb = smem_u32(sm);

    auto issue = [&](int stage, int kc) {
        size_t k0 = (size_t)kc << 5;
        const __nv_bfloat16* srcs[4] = {
            Ah + (size_t)(by * 128) * Kd, Al + (size_t)(by * 128) * Kd,
            Bh + (size_t)(bx * 128) * Kd, Bl + (size_t)(bx * 128) * Kd };
#pragma unroll
        for (int ti = 0; ti < 4; ti++) {
            uint32_t base = smb + (uint32_t)((stage * 4 + ti) * TILE_H) * 2;
            cp_async16(base + (r0 * RS + s0 * 8) * 2,
                       srcs[ti] + (size_t)r0 * Kd + k0 + s0 * 8);
            cp_async16(base + (r1 * RS + s1 * 8) * 2,
                       srcs[ti] + (size_t)r1 * Kd + k0 + s1 * 8);
        }
        cp_commit();
    };

    issue(0, 0);

    const int r8  = lane & 7;
    const int hm  = (lane >> 3) & 1;
    const int hk2 = (lane >> 4) & 1;

    for (int it = 0; it < kiters; it++) {
        int buf = it & 1;
        cp_wait<0>();
        __syncthreads();
        if (it + 1 < kiters) issue(buf ^ 1, it + 1);

        uint32_t sahb = smb + (uint32_t)((buf * 4 + 0) * TILE_H) * 2;
        uint32_t salb = smb + (uint32_t)((buf * 4 + 1) * TILE_H) * 2;
        uint32_t sbhb = smb + (uint32_t)((buf * 4 + 2) * TILE_H) * 2;
        uint32_t sblb = smb + (uint32_t)((buf * 4 + 3) * TILE_H) * 2;

#pragma unroll
        for (int ks = 0; ks < 2; ks++) {
            const int k16 = ks * 16;
            uint32_t ah[2][4], al[2][4];
            uint32_t aoff0 = (uint32_t)((wm + hm * 8 + r8) * RS + k16 + hk2 * 8) * 2;
            uint32_t aoff1 = aoff0 + 16 * RS * 2;
            ldsm4(ah[0], sahb + aoff0);
            ldsm4(ah[1], sahb + aoff1);
            ldsm4(al[0], salb + aoff0);
            ldsm4(al[1], salb + aoff1);
#pragma unroll
            for (int pi = 0; pi < 4; pi++) {
                uint32_t boff = (uint32_t)((wn + pi * 16 + hk2 * 8 + r8) * RS + k16 + hm * 8) * 2;
                uint32_t bh4[4], bl4[4];
                ldsm4(bh4, sbhb + boff);
                ldsm4(bl4, sblb + boff);
                int n0 = pi * 2, n1 = pi * 2 + 1;
                mma16816(acc[0][n0], ah[0], bh4 + 0);
                mma16816(acc[1][n0], ah[1], bh4 + 0);
                mma16816(acc[0][n1], ah[0], bh4 + 2);
                mma16816(acc[1][n1], ah[1], bh4 + 2);
                mma16816(acc[0][n0], ah[0], bl4 + 0);
                mma16816(acc[1][n0], ah[1], bl4 + 0);
                mma16816(acc[0][n1], ah[0], bl4 + 2);
                mma16816(acc[1][n1], ah[1], bl4 + 2);
                mma16816(acc[0][n0], al[0], bh4 + 0);
                mma16816(acc[1][n0], al[1], bh4 + 0);
                mma16816(acc[0][n1], al[0], bh4 + 2);
                mma16816(acc[1][n1], al[1], bh4 + 2);
            }
        }
    }

    __syncthreads();
#pragma unroll
    for (int mi = 0; mi < 2; mi++) {
        int row = by * 128 + wm + mi * 16 + grp;
#pragma unroll
        for (int ni = 0; ni < 8; ni++) {
            int col = bx * 128 + wn + ni * 8 + q * 2;
            float2 v0 = make_float2(acc[mi][ni][0], acc[mi][ni][1]);
            float2 v1 = make_float2(acc[mi][ni][2], acc[mi][ni][3]);
            *reinterpret_cast<float2*>(C + (size_t)row * N + col) = v0;
            *reinterpret_cast<float2*>(C + (size_t)(row + 8) * N + col) = v1;
        }
    }
}

// ---------------------------------------------------------------------------
__global__ void split_kernel(const float* __restrict__ src,
                             __nv_bfloat16* __restrict__ hi,
                             __nv_bfloat16* __restrict__ lo)
{
    size_t i = (size_t)blockIdx.x * 256 + threadIdx.x;
    float v = src[i];
    __nv_bfloat16 h = __float2bfloat16(v);
    hi[i] = h;
    lo[i] = __float2bfloat16(v - __bfloat162float(h));
}

__global__ void transpose_split_kernel(const float* __restrict__ W,
                                       __nv_bfloat16* __restrict__ Th,
                                       __nv_bfloat16* __restrict__ Tl,
                                       int K, int N)
{
    __shared__ float tile[32][33];
    int n0 = blockIdx.x * 32, k0 = blockIdx.y * 32;
    int tx = threadIdx.x, ty = threadIdx.y;
#pragma unroll
    for (int j = 0; j < 4; j++)
        tile[ty + j * 8][tx] = W[(size_t)(k0 + ty + j * 8) * N + n0 + tx];
    __syncthreads();
#pragma unroll
    for (int j = 0; j < 4; j++) {
        float v = tile[tx][ty + j * 8];
        __nv_bfloat16 h = __float2bfloat16(v);
        size_t o = (size_t)(n0 + ty + j * 8) * K + k0 + tx;
        Th[o] = h;
        Tl[o] = __float2bfloat16(v - __bfloat162float(h));
    }
}

// ---------------------------------------------------------------------------
__global__ void __launch_bounds__(256) ba_part_kernel(
    const float* __restrict__ x, const float* __restrict__ w_ba)
{
    int ks = blockIdx.x, by = blockIdx.y;
    __shared__ float As[8][128];
    __shared__ float Bs[8][64];
    int t = threadIdx.x, tx = t & 15, ty = t >> 4;
    float acc[8][4];
#pragma unroll
    for (int i = 0; i < 8; i++)
#pragma unroll
        for (int j = 0; j < 4; j++) acc[i][j] = 0.f;

    int arow = t >> 1, acol4 = (t & 1) * 4;
    int brow = t >> 5, bcol2 = (t & 31) * 2;
    const float* Aptr = x + (size_t)(by * 128 + arow) * Hc + ks * 256;

    for (int k0 = 0; k0 < 256; k0 += 8) {
        float4 a4 = *reinterpret_cast<const float4*>(Aptr + k0 + acol4);
        As[acol4 + 0][arow] = a4.x; As[acol4 + 1][arow] = a4.y;
        As[acol4 + 2][arow] = a4.z; As[acol4 + 3][arow] = a4.w;
        float2 b2 = *reinterpret_cast<const float2*>(
            w_ba + (size_t)(ks * 256 + k0 + brow) * 64 + bcol2);
        Bs[brow][bcol2] = b2.x; Bs[brow][bcol2 + 1] = b2.y;
        __syncthreads();
#pragma unroll
        for (int kk = 0; kk < 8; kk++) {
            float a[8], b[4];
#pragma unroll
            for (int i = 0; i < 8; i++) a[i] = As[kk][ty * 8 + i];
#pragma unroll
            for (int j = 0; j < 4; j++) b[j] = Bs[kk][tx * 4 + j];
#pragma unroll
            for (int i = 0; i < 8; i++)
#pragma unroll
                for (int j = 0; j < 4; j++)
                    acc[i][j] = fmaf(a[i], b[j], acc[i][j]);
        }
        __syncthreads();
    }
    float* dst = g_bapart + (size_t)ks * Mtot * 64;
#pragma unroll
    for (int i = 0; i < 8; i++) {
        int row = by * 128 + ty * 8 + i;
        float4 v = make_float4(acc[i][0], acc[i][1], acc[i][2], acc[i][3]);
        *reinterpret_cast<float4*>(dst + (size_t)row * 64 + tx * 4) = v;
    }
}

__global__ void ba_reduce_kernel()
{
    int i = blockIdx.x * 256 + threadIdx.x;
    float s = 0.f;
#pragma unroll
    for (int ks = 0; ks < 8; ks++) s += g_bapart[(size_t)ks * Mtot * 64 + i];
    g_ba[i] = s;
}

// ---------------------------------------------------------------------------
__global__ void conv_qknorm_kernel(const float* __restrict__ conv_w,
                                   const float* __restrict__ conv_b)
{
    int tid = threadIdx.x;
    int c = blockIdx.x * 256 + tid;
    int m = blockIdx.y;
    int s = m & (Sc - 1);
    int col;
    if (c < 2048)      col = (c >> 7) * 768 + (c & 127);
    else if (c < 4096) { int c2 = c - 2048; col = (c2 >> 7) * 768 + 128 + (c2 & 127); }
    else               { int c3 = c - 4096; col = (c3 >> 8) * 768 + 256 + (c3 & 255); }
    float acc = conv_b[c];
    const float* w = conv_w + c * 4;
#pragma unroll
    for (int j = 0; j < 4; j++) {
        int sp = s - 3 + j;
        if (sp >= 0)
            acc = fmaf(g_qkvz[(size_t)(m - 3 + j) * FQ + col], w[j], acc);
    }
    float val = acc / (1.f + expf(-acc));

    if (c < 4096) {
        float ss = val * val;
#pragma unroll
        for (int o = 16; o > 0; o >>= 1) ss += __shfl_xor_sync(0xffffffffu, ss, o);
        __shared__ float rb[8];
        if ((tid & 31) == 0) rb[tid >> 5] = ss;
        __syncthreads();
        int hw = (tid >> 7) * 4;
        float sum = rb[hw] + rb[hw + 1] + rb[hw + 2] + rb[hw + 3];
        if (c < 2048) {
            float rq = rsqrtf(sum + EPSc) * 0.08838834764831845f;
            g_qn[m * 2048 + c] = val * rq;
        } else {
            float rk = rsqrtf(sum + EPSc);
            g_kn[m * 2048 + (c - 2048)] = val * rk;
        }
    } else {
        g_conv[(size_t)m * CDc + c] = val;
    }
}

__global__ void gbeta_kernel(const float* __restrict__ a_log,
                             const float* __restrict__ dt_bias)
{
    int idx = blockIdx.x * 256 + threadIdx.x;
    int m = idx >> 5, hv = idx & 31;
    int hk = hv >> 1, gi = hv & 1;
    float bval = g_ba[m * 64 + hk * 4 + gi];
    float aval = g_ba[m * 64 + hk * 4 + 2 + gi];
    float x = aval + dt_bias[hv];
    float sp = (x > 20.f) ? x : log1pf(expf(x));
    g_gg[idx]   = -expf(a_log[hv]) * sp;
    g_beta[idx] = 1.f / (1.f + expf(-bval));
}

// ---------------------------------------------------------------------------
// gated delta scan, depth-2 prefetch (3 buffers), ILP-4 reductions.
// 128 blocks = (b,hv,vhalf), 256 threads.
// ---------------------------------------------------------------------------
__global__ void __launch_bounds__(256) scan_kernel()
{
    int bid = blockIdx.x;
    int bb = bid >> 6;
    int r = bid & 63;
    int hv = r >> 1, half = r & 1, hk = hv >> 1;
    int t = threadIdx.x;
    int vl = t & 63, qt = t >> 6, dbase = qt * 32;

    float S[32];
#pragma unroll
    for (int i = 0; i < 32; i++) S[i] = 0.f;

    __shared__ __align__(16) float kq[3][256];
    __shared__ __align__(16) float vsb[3][64];
    __shared__ float gbb[3][2];
    __shared__ float red[4][64], ored[4][64];

    const uint32_t skq = smem_u32(kq);
    const uint32_t svs = smem_u32(vsb);
    const uint32_t sgb = smem_u32(gbb);

    const float* kbase = g_kn + hk * 128;
    const float* qbase = g_qn + hk * 128;
    const float* vbase = g_conv + 4096 + hv * 128 + half * 64;
    const float* gbase = g_gg + hv;
    const float* bbase = g_beta + hv;

    auto prefetch = [&](int buf, int s) {
        int m = bb * Sc + s;
        if (t < 32)
            cp_async16(skq + buf * 1024 + t * 16, kbase + (size_t)m * 2048 + t * 4);
        else if (t < 64)
            cp_async16(skq + buf * 1024 + 512 + (t - 32) * 16,
                       qbase + (size_t)m * 2048 + (t - 32) * 4);
        else if (t < 80)
            cp_async16(svs + buf * 256 + (t - 64) * 16,
                       vbase + (size_t)m * CDc + (t - 64) * 4);
        else if (t == 80)
            cp_async4(sgb + buf * 8, gbase + m * 32);
        else if (t == 81)
            cp_async4(sgb + buf * 8 + 4, bbase + m * 32);
    };

    prefetch(0, 0); cp_commit();
    prefetch(1, 1); cp_commit();

    size_t obase = (size_t)bb * Sc * 4096 + hv * 128 + half * 64;

    for (int s = 0; s < Sc; s++) {
        int buf = s % 3;
        cp_wait<1>();                         // group for step s complete
        __syncthreads();                      // bar1
        if (s + 2 < Sc) { prefetch((s + 2) % 3, s + 2); cp_commit(); }

        if (s > 0 && t < 64)
            g_opre[obase + (size_t)(s - 1) * 4096 + t] =
                ored[0][t] + ored[1][t] + ored[2][t] + ored[3][t];

        float eg   = expf(gbb[buf][0]);
        float beta = gbb[buf][1];
        const float* ks = kq[buf];
        const float* qs = kq[buf] + 128;
        const float* vs = vsb[buf];

        float p0 = 0.f, p1 = 0.f, p2 = 0.f, p3 = 0.f;
#pragma unroll
        for (int d = 0; d < 32; d += 4) {
            S[d]     *= eg;
            S[d + 1] *= eg;
            S[d + 2] *= eg;
            S[d + 3] *= eg;
            p0 = fmaf(ks[dbase + d],     S[d],     p0);
            p1 = fmaf(ks[dbase + d + 1], S[d + 1], p1);
            p2 = fmaf(ks[dbase + d + 2], S[d + 2], p2);
            p3 = fmaf(ks[dbase + d + 3], S[d + 3], p3);
        }
        red[qt][vl] = (p0 + p1) + (p2 + p3);
        __syncthreads();                      // bar2

        float delta = (vs[vl] - (red[0][vl] + red[1][vl] + red[2][vl] + red[3][vl])) * beta;
        float o0 = 0.f, o1 = 0.f, o2 = 0.f, o3 = 0.f;
#pragma unroll
        for (int d = 0; d < 32; d += 4) {
            S[d]     = fmaf(ks[dbase + d],     delta, S[d]);
            S[d + 1] = fmaf(ks[dbase + d + 1], delta, S[d + 1]);
            S[d + 2] = fmaf(ks[dbase + d + 2], delta, S[d + 2]);
            S[d + 3] = fmaf(ks[dbase + d + 3], delta, S[d + 3]);
            o0 = fmaf(qs[dbase + d],     S[d],     o0);
            o1 = fmaf(qs[dbase + d + 1], S[d + 1], o1);
            o2 = fmaf(qs[dbase + d + 2], S[d + 2], o2);
            o3 = fmaf(qs[dbase + d + 3], S[d + 3], o3);
        }
        ored[qt][vl] = (o0 + o1) + (o2 + o3);
    }
    __syncthreads();
    if (t < 64)
        g_opre[obase + (size_t)(Sc - 1) * 4096 + t] =
            ored[0][t] + ored[1][t] + ored[2][t] + ored[3][t];
}

// ---------------------------------------------------------------------------
__global__ void gate_norm_kernel(const float* __restrict__ norm_w)
{
    int m = blockIdx.x, hv = blockIdx.y, d = threadIdx.x;
    int hk = hv >> 1, gi = hv & 1;
    float z = g_qkvz[(size_t)m * FQ + hk * 768 + 512 + gi * 128 + d];
    float o = g_opre[(size_t)m * 4096 + hv * 128 + d] * (z / (1.f + expf(-z)));
    float ss = o * o;
#pragma unroll
    for (int off = 16; off > 0; off >>= 1) ss += __shfl_xor_sync(0xffffffffu, ss, off);
    __shared__ float rb[4];
    if ((d & 31) == 0) rb[d >> 5] = ss;
    __syncthreads();
    float sum = rb[0] + rb[1] + rb[2] + rb[3];
    float rs = rsqrtf(sum * (1.f / 128.f) + EPSc);
    float v = o * rs * norm_w[d];
    __nv_bfloat16 h = __float2bfloat16(v);
    size_t idx = (size_t)m * 4096 + hv * 128 + d;
    g_ohi[idx] = h;
    g_olo[idx] = __float2bfloat16(v - __bfloat162float(h));
}

// ---------------------------------------------------------------------------
extern "C" void kernel_launch(void* const* d_in, const int* in_sizes, int n_in,
                              void* d_out, int out_size)
{
    const float* x       = (const float*)d_in[0];
    const float* w_qkvz  = (const float*)d_in[1];
    const float* w_ba    = (const float*)d_in[2];
    const float* a_log   = (const float*)d_in[3];
    const float* dt_bias = (const float*)d_in[4];
    const float* conv_w  = (const float*)d_in[5];
    const float* conv_b  = (const float*)d_in[6];
    const float* norm_w  = (const float*)d_in[7];
    const float* w_o     = (const float*)d_in[8];
    float* out = (float*)d_out;

    float *p_qkvz;
    __nv_bfloat16 *p_xhi, *p_xlo, *p_bqhi, *p_bqlo, *p_bohi, *p_bolo, *p_ohi, *p_olo;
    cudaGetSymbolAddress((void**)&p_qkvz, g_qkvz);
    cudaGetSymbolAddress((void**)&p_xhi,  g_xhi);
    cudaGetSymbolAddress((void**)&p_xlo,  g_xlo);
    cudaGetSymbolAddress((void**)&p_bqhi, g_bqhi);
    cudaGetSymbolAddress((void**)&p_bqlo, g_bqlo);
    cudaGetSymbolAddress((void**)&p_bohi, g_bohi);
    cudaGetSymbolAddress((void**)&p_bolo, g_bolo);
    cudaGetSymbolAddress((void**)&p_ohi,  g_ohi);
    cudaGetSymbolAddress((void**)&p_olo,  g_olo);

    cudaFuncSetAttribute(mma_gemm_kernel,
                         cudaFuncAttributeMaxDynamicSharedMemorySize, GEMM_SMEM);

    split_kernel<<<(Mtot * Hc) / 256, 256>>>(x, p_xhi, p_xlo);
    transpose_split_kernel<<<dim3(FQ / 32, Hc / 32), dim3(32, 8)>>>(w_qkvz, p_bqhi, p_bqlo, Hc, FQ);
    transpose_split_kernel<<<dim3(Hc / 32, 4096 / 32), dim3(32, 8)>>>(w_o, p_bohi, p_bolo, 4096, Hc);

    // K1: qkvz = x @ w_qkvz  (1D swizzled grid)
    mma_gemm_kernel<<<(FQ / 128) * (Mtot / 128), 256, GEMM_SMEM>>>(
        p_xhi, p_xlo, p_bqhi, p_bqlo, p_qkvz, Hc, FQ);
    // K2: ba = x @ w_ba (split-K x8 + reduce)
    ba_part_kernel<<<dim3(8, Mtot / 128), 256>>>(x, w_ba);
    ba_reduce_kernel<<<(Mtot * 64) / 256, 256>>>();
    // K3+K4: conv + silu + q/k l2norm
    conv_qknorm_kernel<<<dim3(CDc / 256, Mtot), 256>>>(conv_w, conv_b);
    // K5: gates
    gbeta_kernel<<<(Mtot * HVc) / 256, 256>>>(a_log, dt_bias);
    // K6: recurrent scan
    scan_kernel<<<128, 256>>>();
    // K7: gate + rmsnorm + bf16 split
    gate_norm_kernel<<<dim3(Mtot, HVc), 128>>>(norm_w);
    // K8: out = o @ w_o
    mma_gemm_kernel<<<(Hc / 128) * (Mtot / 128), 256, GEMM_SMEM>>>(
        p_ohi, p_olo, p_bohi, p_bolo, out, 4096, Hc);
}